// round 9
// baseline (speedup 1.0000x reference)
#include <cuda_runtime.h>
#include <cuda_bf16.h>
#include <math.h>

#define NB 32
#define NG 60
#define NC 80
#define NA 8400
#define A0 6400
#define A1 8000
#define TK 10
#define NCH 33   // ceil(NA/256)
#define NCH64 132 // ceil(NA/64)
#define AW 4     // warps (g's) per assign block
#define AGX 15   // ceil(NG/AW)

// ---------------- device scratch ----------------
__device__ float4 d_box[NB * NA];
__device__ float  d_obj[NB * NA];
__device__ unsigned char d_fg[NB * NA];
__device__ float4 d_geo[NA];
__device__ int    d_ccnt[NB * NCH];
__device__ int    d_fglist[NB * NA];
__device__ int    d_fgpos[NB * NA];
__device__ int    d_fgcnt[NB];
__device__ float4 d_boxC[NB * NA];
__device__ float4 d_geoC[NB * NA];
__device__ float  d_b0sC[NB * NA];
__device__ float  d_spsC[NB * NA];
__device__ float  d_dcoC[(size_t)NB * NC * NA];
__device__ int    d_cnt[NB * NA];
__device__ int    d_lastg[NB * NA];
__device__ int    d_matched[NB * NA];
__device__ float  d_prediou[NB * NA];
__device__ double d_acc[4];

__device__ __forceinline__ float iou_fn(float gx, float gy, float gw, float gh, float4 pb) {
    float tlx = fmaxf(gx - gw * 0.5f, pb.x - pb.z * 0.5f);
    float tly = fmaxf(gy - gh * 0.5f, pb.y - pb.w * 0.5f);
    float brx = fminf(gx + gw * 0.5f, pb.x + pb.z * 0.5f);
    float bry = fminf(gy + gh * 0.5f, pb.y + pb.w * 0.5f);
    bool en = (tlx < brx) && (tly < bry);
    float inter = en ? (brx - tlx) * (bry - tly) : 0.f;
    return inter / (gw * gh + pb.z * pb.w - inter + 1e-16f);
}

__device__ __forceinline__ float cost_fn(float gx, float gy, float gw, float gh,
                                         float iou, float cxa, float cya, float st,
                                         float b0s, float dco, bool valid, float c0) {
    const float R = 2.5f;
    bool in_box = (cxa > gx - 0.5f * gw) && (cxa < gx + 0.5f * gw) &&
                  (cya > gy - 0.5f * gh) && (cya < gy + 0.5f * gh);
    bool in_ctr = (cxa > gx - R * st) && (cxa < gx + R * st) &&
                  (cya > gy - R * st) && (cya < gy + R * st);
    bool in_both = in_box && in_ctr;
    float lt = (iou == 0.f) ? c0 : -logf(iou + 1e-8f);
    float cost = b0s + dco;
    cost += 3.0f * lt;
    cost += 100000.0f * (1.0f - (in_both ? 1.f : 0.f));
    cost += valid ? 0.f : 1000000000.0f;
    return cost;
}

// ---------------- kernels ----------------
__global__ void k_decode_fg(const float* __restrict__ f8,
                            const float* __restrict__ f16,
                            const float* __restrict__ f32_,
                            const float* __restrict__ gtb,
                            const int* __restrict__ ngts) {
    __shared__ float4 sgt[NG];
    int b = blockIdx.y;
    int n = ngts[b];
    if (threadIdx.x < NG) {
        const float* gbp = gtb + ((size_t)b * NG + threadIdx.x) * 4;
        sgt[threadIdx.x] = make_float4(gbp[0], gbp[1], gbp[2], gbp[3]);
    }
    __syncthreads();
    int a = blockIdx.x * blockDim.x + threadIdx.x;
    bool fg = false;
    if (a < NA) {
        int i = b * NA + a;
        d_cnt[i] = 0;
        if (i < 4) d_acc[i] = 0.0;
        const float* f; int hw, HW, W; float st;
        if (a < A0)      { f = f8;   hw = a;      HW = 6400; W = 80; st = 8.f;  }
        else if (a < A1) { f = f16;  hw = a - A0; HW = 1600; W = 40; st = 16.f; }
        else             { f = f32_; hw = a - A1; HW = 400;  W = 20; st = 32.f; }
        int xi = hw % W, yi = hw / W;
        float gx = (float)xi, gy = (float)yi;
        float cxa = (gx + 0.5f) * st, cya = (gy + 0.5f) * st;
        if (b == 0) d_geo[a] = make_float4(cxa, cya, st, 0.f);
        const float* base = f + (size_t)b * (5 + NC) * HW + hw;
        float tx = base[0 * HW], ty = base[(size_t)1 * HW];
        float tw = base[(size_t)2 * HW], th = base[(size_t)3 * HW];
        float to = base[(size_t)4 * HW];
        d_box[i] = make_float4((tx + gx) * st, (ty + gy) * st, expf(tw) * st, expf(th) * st);
        d_obj[i] = to;
        const float R = 2.5f;
        for (int g = 0; g < n; g++) {
            float4 gb = sgt[g];
            bool in_box = (cxa > gb.x - 0.5f * gb.z) && (cxa < gb.x + 0.5f * gb.z) &&
                          (cya > gb.y - 0.5f * gb.w) && (cya < gb.y + 0.5f * gb.w);
            bool in_ctr = (cxa > gb.x - R * st) && (cxa < gb.x + R * st) &&
                          (cya > gb.y - R * st) && (cya < gb.y + R * st);
            fg = fg || in_box || in_ctr;
        }
        d_fg[i] = fg ? 1 : 0;
    }
    int c = __syncthreads_count(fg ? 1 : 0);
    if (threadIdx.x == 0) d_ccnt[b * NCH + blockIdx.x] = c;
}

__global__ void k_compact() {
    __shared__ int swcnt[8];
    __shared__ int swoff[8];
    __shared__ int s_base;
    int b = blockIdx.y, ch = blockIdx.x, tid = threadIdx.x;
    int warp = tid >> 5, lane = tid & 31;
    if (warp == 0) {
        int v = 0;
        for (int c = lane; c < ch; c += 32) v += d_ccnt[b * NCH + c];
        for (int o = 16; o; o >>= 1) v += __shfl_xor_sync(0xffffffffu, v, o);
        if (lane == 0) s_base = v;
    }
    int a = ch * 256 + tid;
    bool flag = (a < NA) && d_fg[b * NA + a];
    unsigned bal = __ballot_sync(0xffffffffu, flag);
    int intra = __popc(bal & ((1u << lane) - 1u));
    if (lane == 0) swcnt[warp] = __popc(bal);
    __syncthreads();
    if (tid == 0) {
        int s = 0;
        for (int w = 0; w < 8; w++) { swoff[w] = s; s += swcnt[w]; }
        if (ch == NCH - 1) d_fgcnt[b] = s_base + s;
    }
    __syncthreads();
    if (flag) {
        int j = s_base + swoff[warp] + intra;
        d_fglist[b * NA + j] = a;
        d_fgpos[b * NA + a] = j;
        d_boxC[b * NA + j] = d_box[b * NA + a];
        d_geoC[b * NA + j] = d_geo[a];
    }
}

__global__ void k_clsprep(const float* __restrict__ f8, const float* __restrict__ f16,
                          const float* __restrict__ f32_) {
    __shared__ float s_b0[256];
    __shared__ float s_sp[256];
    int b = blockIdx.y;
    int tid = threadIdx.x;
    int jl = tid & 63;
    int grp = tid >> 6;
    int j = blockIdx.x * 64 + jl;
    int cnt = d_fgcnt[b];
    float b0s = 0.f, sps = 0.f;
    if (j < cnt) {
        int a = d_fglist[b * NA + j];
        const float* f; int hw, HW;
        if (a < A0)      { f = f8;   hw = a;      HW = 6400; }
        else if (a < A1) { f = f16;  hw = a - A0; HW = 1600; }
        else             { f = f32_; hw = a - A1; HW = 400;  }
        const float* base = f + (size_t)b * (5 + NC) * HW + hw;
        float to = d_obj[b * NA + a];
        float eo = expf(-fabsf(to));
        float so = (to >= 0.f) ? 1.f / (1.f + eo) : eo / (1.f + eo);
        float spo = fmaxf(-to, 0.f) + log1pf(eo);
        int c0i = grp * 20;
#pragma unroll 5
        for (int c = c0i; c < c0i + 20; c++) {
            float x = base[(size_t)(5 + c) * HW];
            float e = expf(-fabsf(x));
            float r = 1.f / (1.f + e);
            float sc = (x >= 0.f) ? r : e * r;
            float l1pe = log1pf(e);
            float sp = fmaxf(x, 0.f) + l1pe;
            float spn = sp - x;
            float p = sqrtf(sc * so);
            p = fminf(fmaxf(p, 1e-7f), 1.f - 1e-7f);
            float bce1 = 0.5f * (spn + spo);
            float bce0 = -logf(1.f - p);
            b0s += bce0;
            d_dcoC[((size_t)b * NC + c) * NA + j] = bce1 - bce0;
            sps += sp;
        }
    }
    s_b0[tid] = b0s;
    s_sp[tid] = sps;
    __syncthreads();
    if (grp == 0 && j < cnt) {
        float tb = (s_b0[jl] + s_b0[64 + jl]) + (s_b0[128 + jl] + s_b0[192 + jl]);
        float ts = (s_sp[jl] + s_sp[64 + jl]) + (s_sp[128 + jl] + s_sp[192 + jl]);
        d_b0sC[b * NA + j] = tb;
        d_spsC[b * NA + j] = ts;
    }
}

// warp-per-(b,g) fused cost+iou + top-k + inline scatter; 4 warps/block, no __syncthreads
__global__ void k_assign(const float* __restrict__ gtb, const int* __restrict__ gtc,
                         const int* __restrict__ ngts) {
    __shared__ float s_v[AW][32 * TK];
    __shared__ int   s_i[AW][32 * TK];

    int w = threadIdx.x >> 5, lane = threadIdx.x & 31;
    int g = blockIdx.x * AW + w;
    int b = blockIdx.y;
    if (g >= NG || g >= ngts[b]) return;

    const float c0 = -logf(1e-8f);

    const float* gb = gtb + ((size_t)b * NG + g) * 4;
    float gx = gb[0], gy = gb[1], gw = gb[2], gh = gb[3];
    int gc = gtc[b * NG + g];
    int cnt = d_fgcnt[b];

    const float4* boxp = d_boxC + b * NA;
    const float4* geop = d_geoC + b * NA;
    const float* b0p = d_b0sC + b * NA;
    const float* dcop = d_dcoC + ((size_t)b * NC + gc) * NA;

    float iv[TK]; int ii[TK];
    float cv[TK]; int ci[TK];
#pragma unroll
    for (int k = 0; k < TK; k++) { iv[k] = -1.f; ii[k] = 0x7fffffff; cv[k] = 3.4e38f; ci[k] = 0x7fffffff; }

    for (int j = lane; j < cnt; j += 32) {
        float4 pb = boxp[j];
        float iou = iou_fn(gx, gy, gw, gh, pb);
        if (iou > iv[TK - 1] || (iou == iv[TK - 1] && j < ii[TK - 1])) {
            iv[TK - 1] = iou; ii[TK - 1] = j;
#pragma unroll
            for (int k = TK - 1; k > 0; k--) {
                if (iv[k] > iv[k - 1] || (iv[k] == iv[k - 1] && ii[k] < ii[k - 1])) {
                    float tv = iv[k]; iv[k] = iv[k - 1]; iv[k - 1] = tv;
                    int ti = ii[k]; ii[k] = ii[k - 1]; ii[k - 1] = ti;
                }
            }
        }
        float4 ge = geop[j];
        float cost = cost_fn(gx, gy, gw, gh, iou, ge.x, ge.y, ge.z, b0p[j], dcop[j], true, c0);
        if (cost < cv[TK - 1] || (cost == cv[TK - 1] && j < ci[TK - 1])) {
            cv[TK - 1] = cost; ci[TK - 1] = j;
#pragma unroll
            for (int k = TK - 1; k > 0; k--) {
                if (cv[k] < cv[k - 1] || (cv[k] == cv[k - 1] && ci[k] < ci[k - 1])) {
                    float tv = cv[k]; cv[k] = cv[k - 1]; cv[k - 1] = tv;
                    int ti = ci[k]; ci[k] = ci[k - 1]; ci[k - 1] = ti;
                }
            }
        }
    }

    // ---- warp merge: iou (max) -> dyn_k ----
#pragma unroll
    for (int k = 0; k < TK; k++) { s_v[w][lane * TK + k] = iv[k]; s_i[w][lane * TK + k] = ii[k]; }
    __syncwarp();
    int head = 0;
    float ksum = 0.f;
    for (int r = 0; r < TK; r++) {
        float mv; int mi;
        if (head < TK) { mv = s_v[w][lane * TK + head]; mi = s_i[w][lane * TK + head]; }
        else           { mv = -2.f; mi = 0x7fffffff; }
        int ml = lane;
        for (int o = 16; o; o >>= 1) {
            float ov = __shfl_xor_sync(0xffffffffu, mv, o);
            int oi = __shfl_xor_sync(0xffffffffu, mi, o);
            int ol = __shfl_xor_sync(0xffffffffu, ml, o);
            if (ov > mv || (ov == mv && oi < mi)) { mv = ov; mi = oi; ml = ol; }
        }
        ksum += fmaxf(mv, 0.f);
        if (lane == ml) head++;
    }
    int dk = (int)ksum;
    if (dk < 1) dk = 1;

    // ---- warp merge: cost (min) -> pos + inline scatter ----
#pragma unroll
    for (int k = 0; k < TK; k++) { s_v[w][lane * TK + k] = cv[k]; s_i[w][lane * TK + k] = ci[k]; }
    __syncwarp();
    head = 0;
    int pa[TK];
    for (int r = 0; r < TK; r++) {
        float mv; int mi;
        if (head < TK) { mv = s_v[w][lane * TK + head]; mi = s_i[w][lane * TK + head]; }
        else           { mv = 3.5e38f; mi = 0x7fffffff; }
        int ml = lane;
        for (int o = 16; o; o >>= 1) {
            float ov = __shfl_xor_sync(0xffffffffu, mv, o);
            int oi = __shfl_xor_sync(0xffffffffu, mi, o);
            int ol = __shfl_xor_sync(0xffffffffu, ml, o);
            if (ov < mv || (ov == mv && oi < mi)) { mv = ov; mi = oi; ml = ol; }
        }
        pa[r] = mi;
        if (lane == ml) head++;
    }
    if (lane == 0) {
#pragma unroll
        for (int r = 0; r < TK; r++) {
            if (r < dk) {
                int a = d_fglist[b * NA + pa[r]];
                atomicAdd(&d_cnt[b * NA + a], 1);
                d_lastg[b * NA + a] = g;
            }
        }
    }
}

__global__ void k_resolve(const float* __restrict__ gtb, const int* __restrict__ gtc,
                          const int* __restrict__ ngts) {
    int i = blockIdx.x * blockDim.x + threadIdx.x;
    if (i >= NB * NA) return;
    int c = d_cnt[i];
    if (c == 0) { d_matched[i] = -1; d_prediou[i] = 0.f; return; }
    int b = i / NA, a = i % NA;
    float4 pb = d_box[i];
    int mg;
    if (c == 1) {
        mg = d_lastg[i];
    } else {
        const float c0 = -logf(1e-8f);
        int n = ngts[b];
        int j = d_fgpos[i];
        float4 ge = d_geo[a];
        float b0s = d_b0sC[b * NA + j];
        float best = 3.5e38f; int bi = 0;
        for (int g = 0; g < NG; g++) {
            const float* gb = gtb + ((size_t)b * NG + g) * 4;
            float gx = gb[0], gy = gb[1], gw = gb[2], gh = gb[3];
            int gc = gtc[b * NG + g];
            float iou = iou_fn(gx, gy, gw, gh, pb);
            float dco = d_dcoC[((size_t)b * NC + gc) * NA + j];
            float cv = cost_fn(gx, gy, gw, gh, iou, ge.x, ge.y, ge.z, b0s, dco, g < n, c0);
            if (cv < best) { best = cv; bi = g; }
        }
        mg = bi;
    }
    d_matched[i] = mg;
    const float* gb = gtb + ((size_t)b * NG + mg) * 4;
    d_prediou[i] = iou_fn(gb[0], gb[1], gb[2], gb[3], pb);
}

__global__ void k_loss(const float* __restrict__ gtb, const int* __restrict__ gtc,
                       const float* __restrict__ f8, const float* __restrict__ f16,
                       const float* __restrict__ f32_) {
    __shared__ float s1[256], s2[256], s3[256];
    __shared__ int   s4[256];
    int tid = threadIdx.x;
    int i = blockIdx.x * blockDim.x + tid;
    float liou = 0.f, lobj = 0.f, lcls = 0.f; int nfg = 0;
    if (i < NB * NA) {
        int b = i / NA, a = i % NA;
        int mg = d_matched[i];
        bool fg = mg >= 0;
        float tgt = fg ? 0.9f : 0.f;
        float x = d_obj[i];
        lobj = fmaxf(x, 0.f) - x * tgt + log1pf(expf(-fabsf(x)));
        if (fg) {
            nfg = 1;
            const float* gb = gtb + ((size_t)b * NG + mg) * 4;
            float gx = gb[0], gy = gb[1], gw = gb[2], gh = gb[3];
            float4 pb = d_box[i];
            float tlx = fmaxf(pb.x - pb.z * 0.5f, gx - gw * 0.5f);
            float tly = fmaxf(pb.y - pb.w * 0.5f, gy - gh * 0.5f);
            float brx = fminf(pb.x + pb.z * 0.5f, gx + gw * 0.5f);
            float bry = fminf(pb.y + pb.w * 0.5f, gy + gh * 0.5f);
            bool en = (tlx < brx) && (tly < bry);
            float inter = en ? (brx - tlx) * (bry - tly) : 0.f;
            float uni = pb.z * pb.w + gw * gh - inter;
            float iou = inter / (uni + 1e-16f);
            liou = 1.f - iou * iou;
            int gc = gtc[b * NG + mg];
            const float* f; int hw, HW;
            if (a < A0)      { f = f8;   hw = a;      HW = 6400; }
            else if (a < A1) { f = f16;  hw = a - A0; HW = 1600; }
            else             { f = f32_; hw = a - A1; HW = 400;  }
            float cl = f[((size_t)b * (5 + NC) + 5 + gc) * HW + hw];
            lcls = d_spsC[b * NA + d_fgpos[i]] - cl * d_prediou[i];
        }
    }
    s1[tid] = liou; s2[tid] = lobj; s3[tid] = lcls; s4[tid] = nfg;
    __syncthreads();
    for (int s = 128; s > 0; s >>= 1) {
        if (tid < s) {
            s1[tid] += s1[tid + s]; s2[tid] += s2[tid + s];
            s3[tid] += s3[tid + s]; s4[tid] += s4[tid + s];
        }
        __syncthreads();
    }
    if (tid == 0) {
        atomicAdd(&d_acc[0], (double)s1[0]);
        atomicAdd(&d_acc[1], (double)s2[0]);
        atomicAdd(&d_acc[2], (double)s3[0]);
        atomicAdd(&d_acc[3], (double)s4[0]);
    }
}

__global__ void k_final(float* out) {
    double nfg = d_acc[3];
    if (nfg < 1.0) nfg = 1.0;
    out[0] = (float)((5.0 * d_acc[0] + d_acc[1] + d_acc[2]) / nfg);
}

// ---------------- launch ----------------
extern "C" void kernel_launch(void* const* d_in, const int* in_sizes, int n_in,
                              void* d_out, int out_size) {
    const float* f8   = (const float*)d_in[0];
    const float* f16  = (const float*)d_in[1];
    const float* f32_ = (const float*)d_in[2];
    const float* gtb  = (const float*)d_in[3];
    const int*   gtc  = (const int*)d_in[4];
    const int*   ngts = (const int*)d_in[5];
    float* out = (float*)d_out;

    const int NBA = NB * NA;
    const int T = 256;
    const int GBA = (NBA + T - 1) / T;

    k_decode_fg<<<dim3(NCH, NB), T>>>(f8, f16, f32_, gtb, ngts);
    k_compact<<<dim3(NCH, NB), T>>>();
    k_clsprep<<<dim3(NCH64, NB), T>>>(f8, f16, f32_);
    k_assign<<<dim3(AGX, NB), AW * 32>>>(gtb, gtc, ngts);
    k_resolve<<<GBA, T>>>(gtb, gtc, ngts);
    k_loss<<<GBA, T>>>(gtb, gtc, f8, f16, f32_);
    k_final<<<1, 1>>>(out);
}

// round 10
// speedup vs baseline: 1.2780x; 1.2780x over previous
#include <cuda_runtime.h>
#include <cuda_bf16.h>
#include <math.h>

#define NB 32
#define NG 60
#define NC 80
#define NA 8400
#define A0 6400
#define A1 8000
#define TK 10
#define NCH 33   // ceil(NA/256)
#define NCH64 132 // ceil(NA/64)
#define AT 128   // assign block threads

// ---------------- device scratch ----------------
__device__ float4 d_box[NB * NA];
__device__ float  d_obj[NB * NA];
__device__ unsigned char d_fg[NB * NA];
__device__ float4 d_geo[NA];
__device__ int    d_ccnt[NB * NCH];
__device__ int    d_fglist[NB * NA];
__device__ int    d_fgpos[NB * NA];
__device__ int    d_fgcnt[NB];
__device__ float4 d_boxC[NB * NA];
__device__ float4 d_geoC[NB * NA];
__device__ float  d_b0sC[NB * NA];
__device__ float  d_spsC[NB * NA];
__device__ float  d_dcoC[(size_t)NB * NC * NA];
__device__ int    d_cnt[NB * NA];
__device__ int    d_lastg[NB * NA];
__device__ int    d_matched[NB * NA];
__device__ float  d_prediou[NB * NA];
__device__ double d_acc[4];

__device__ __forceinline__ float iou_fn(float gx, float gy, float gw, float gh, float4 pb) {
    float tlx = fmaxf(gx - gw * 0.5f, pb.x - pb.z * 0.5f);
    float tly = fmaxf(gy - gh * 0.5f, pb.y - pb.w * 0.5f);
    float brx = fminf(gx + gw * 0.5f, pb.x + pb.z * 0.5f);
    float bry = fminf(gy + gh * 0.5f, pb.y + pb.w * 0.5f);
    bool en = (tlx < brx) && (tly < bry);
    float inter = en ? (brx - tlx) * (bry - tly) : 0.f;
    return inter / (gw * gh + pb.z * pb.w - inter + 1e-16f);
}

__device__ __forceinline__ float cost_fn(float gx, float gy, float gw, float gh,
                                         float iou, float cxa, float cya, float st,
                                         float b0s, float dco, bool valid, float c0) {
    const float R = 2.5f;
    bool in_box = (cxa > gx - 0.5f * gw) && (cxa < gx + 0.5f * gw) &&
                  (cya > gy - 0.5f * gh) && (cya < gy + 0.5f * gh);
    bool in_ctr = (cxa > gx - R * st) && (cxa < gx + R * st) &&
                  (cya > gy - R * st) && (cya < gy + R * st);
    bool in_both = in_box && in_ctr;
    float lt = (iou == 0.f) ? c0 : -logf(iou + 1e-8f);
    float cost = b0s + dco;
    cost += 3.0f * lt;
    cost += 100000.0f * (1.0f - (in_both ? 1.f : 0.f));
    cost += valid ? 0.f : 1000000000.0f;
    return cost;
}

// ---------------- kernels ----------------
__global__ void k_decode_fg(const float* __restrict__ f8,
                            const float* __restrict__ f16,
                            const float* __restrict__ f32_,
                            const float* __restrict__ gtb,
                            const int* __restrict__ ngts) {
    __shared__ float4 sgt[NG];
    int b = blockIdx.y;
    int n = ngts[b];
    if (threadIdx.x < NG) {
        const float* gbp = gtb + ((size_t)b * NG + threadIdx.x) * 4;
        sgt[threadIdx.x] = make_float4(gbp[0], gbp[1], gbp[2], gbp[3]);
    }
    __syncthreads();
    int a = blockIdx.x * blockDim.x + threadIdx.x;
    bool fg = false;
    if (a < NA) {
        int i = b * NA + a;
        d_cnt[i] = 0;
        if (i < 4) d_acc[i] = 0.0;
        const float* f; int hw, HW, W; float st;
        if (a < A0)      { f = f8;   hw = a;      HW = 6400; W = 80; st = 8.f;  }
        else if (a < A1) { f = f16;  hw = a - A0; HW = 1600; W = 40; st = 16.f; }
        else             { f = f32_; hw = a - A1; HW = 400;  W = 20; st = 32.f; }
        int xi = hw % W, yi = hw / W;
        float gx = (float)xi, gy = (float)yi;
        float cxa = (gx + 0.5f) * st, cya = (gy + 0.5f) * st;
        if (b == 0) d_geo[a] = make_float4(cxa, cya, st, 0.f);
        const float* base = f + (size_t)b * (5 + NC) * HW + hw;
        float tx = base[0 * HW], ty = base[(size_t)1 * HW];
        float tw = base[(size_t)2 * HW], th = base[(size_t)3 * HW];
        float to = base[(size_t)4 * HW];
        d_box[i] = make_float4((tx + gx) * st, (ty + gy) * st, expf(tw) * st, expf(th) * st);
        d_obj[i] = to;
        const float R = 2.5f;
        for (int g = 0; g < n; g++) {
            float4 gb = sgt[g];
            bool in_box = (cxa > gb.x - 0.5f * gb.z) && (cxa < gb.x + 0.5f * gb.z) &&
                          (cya > gb.y - 0.5f * gb.w) && (cya < gb.y + 0.5f * gb.w);
            bool in_ctr = (cxa > gb.x - R * st) && (cxa < gb.x + R * st) &&
                          (cya > gb.y - R * st) && (cya < gb.y + R * st);
            fg = fg || in_box || in_ctr;
        }
        d_fg[i] = fg ? 1 : 0;
    }
    int c = __syncthreads_count(fg ? 1 : 0);
    if (threadIdx.x == 0) d_ccnt[b * NCH + blockIdx.x] = c;
}

__global__ void k_compact() {
    __shared__ int swcnt[8];
    __shared__ int swoff[8];
    __shared__ int s_base;
    int b = blockIdx.y, ch = blockIdx.x, tid = threadIdx.x;
    int warp = tid >> 5, lane = tid & 31;
    if (warp == 0) {
        int v = 0;
        for (int c = lane; c < ch; c += 32) v += d_ccnt[b * NCH + c];
        for (int o = 16; o; o >>= 1) v += __shfl_xor_sync(0xffffffffu, v, o);
        if (lane == 0) s_base = v;
    }
    int a = ch * 256 + tid;
    bool flag = (a < NA) && d_fg[b * NA + a];
    unsigned bal = __ballot_sync(0xffffffffu, flag);
    int intra = __popc(bal & ((1u << lane) - 1u));
    if (lane == 0) swcnt[warp] = __popc(bal);
    __syncthreads();
    if (tid == 0) {
        int s = 0;
        for (int w = 0; w < 8; w++) { swoff[w] = s; s += swcnt[w]; }
        if (ch == NCH - 1) d_fgcnt[b] = s_base + s;
    }
    __syncthreads();
    if (flag) {
        int j = s_base + swoff[warp] + intra;
        d_fglist[b * NA + j] = a;
        d_fgpos[b * NA + a] = j;
        d_boxC[b * NA + j] = d_box[b * NA + a];
        d_geoC[b * NA + j] = d_geo[a];
    }
}

__global__ void k_clsprep(const float* __restrict__ f8, const float* __restrict__ f16,
                          const float* __restrict__ f32_) {
    __shared__ float s_b0[256];
    __shared__ float s_sp[256];
    int b = blockIdx.y;
    int tid = threadIdx.x;
    int jl = tid & 63;
    int grp = tid >> 6;
    int j = blockIdx.x * 64 + jl;
    int cnt = d_fgcnt[b];
    float b0s = 0.f, sps = 0.f;
    if (j < cnt) {
        int a = d_fglist[b * NA + j];
        const float* f; int hw, HW;
        if (a < A0)      { f = f8;   hw = a;      HW = 6400; }
        else if (a < A1) { f = f16;  hw = a - A0; HW = 1600; }
        else             { f = f32_; hw = a - A1; HW = 400;  }
        const float* base = f + (size_t)b * (5 + NC) * HW + hw;
        float to = d_obj[b * NA + a];
        float eo = expf(-fabsf(to));
        float so = (to >= 0.f) ? 1.f / (1.f + eo) : eo / (1.f + eo);
        float spo = fmaxf(-to, 0.f) + log1pf(eo);
        int c0i = grp * 20;
#pragma unroll 5
        for (int c = c0i; c < c0i + 20; c++) {
            float x = base[(size_t)(5 + c) * HW];
            float e = expf(-fabsf(x));
            float r = 1.f / (1.f + e);
            float sc = (x >= 0.f) ? r : e * r;
            float l1pe = log1pf(e);
            float sp = fmaxf(x, 0.f) + l1pe;
            float spn = sp - x;
            float p = sqrtf(sc * so);
            p = fminf(fmaxf(p, 1e-7f), 1.f - 1e-7f);
            float bce1 = 0.5f * (spn + spo);
            float bce0 = -logf(1.f - p);
            b0s += bce0;
            d_dcoC[((size_t)b * NC + c) * NA + j] = bce1 - bce0;
            sps += sp;
        }
    }
    s_b0[tid] = b0s;
    s_sp[tid] = sps;
    __syncthreads();
    if (grp == 0 && j < cnt) {
        float tb = (s_b0[jl] + s_b0[64 + jl]) + (s_b0[128 + jl] + s_b0[192 + jl]);
        float ts = (s_sp[jl] + s_sp[64 + jl]) + (s_sp[128 + jl] + s_sp[192 + jl]);
        d_b0sC[b * NA + j] = tb;
        d_spsC[b * NA + j] = ts;
    }
}

// block-per-(b,g), 128 threads; dual smem-staged lists; warp0 merges iou, warp1 merges cost in parallel
__global__ void k_assign(const float* __restrict__ gtb, const int* __restrict__ gtc,
                         const int* __restrict__ ngts) {
    __shared__ float s_iv[AT * TK];
    __shared__ int   s_ii[AT * TK];
    __shared__ float s_cv[AT * TK];
    __shared__ int   s_ci[AT * TK];
    __shared__ int   s_pos[TK];
    __shared__ int   s_dk;

    int tid = threadIdx.x;
    int warp = tid >> 5, lane = tid & 31;
    int g = blockIdx.x, b = blockIdx.y;
    if (g >= ngts[b]) return;

    const float c0 = -logf(1e-8f);

    const float* gb = gtb + ((size_t)b * NG + g) * 4;
    float gx = gb[0], gy = gb[1], gw = gb[2], gh = gb[3];
    int gc = gtc[b * NG + g];
    int cnt = d_fgcnt[b];

    const float4* boxp = d_boxC + b * NA;
    const float4* geop = d_geoC + b * NA;
    const float* b0p = d_b0sC + b * NA;
    const float* dcop = d_dcoC + ((size_t)b * NC + gc) * NA;

    float iv[TK]; int ii[TK];
    float cv[TK]; int ci[TK];
#pragma unroll
    for (int k = 0; k < TK; k++) { iv[k] = -1.f; ii[k] = 0x7fffffff; cv[k] = 3.4e38f; ci[k] = 0x7fffffff; }

    for (int j = tid; j < cnt; j += AT) {
        float4 pb = boxp[j];
        float iou = iou_fn(gx, gy, gw, gh, pb);
        if (iou > iv[TK - 1] || (iou == iv[TK - 1] && j < ii[TK - 1])) {
            iv[TK - 1] = iou; ii[TK - 1] = j;
#pragma unroll
            for (int k = TK - 1; k > 0; k--) {
                if (iv[k] > iv[k - 1] || (iv[k] == iv[k - 1] && ii[k] < ii[k - 1])) {
                    float tv = iv[k]; iv[k] = iv[k - 1]; iv[k - 1] = tv;
                    int ti = ii[k]; ii[k] = ii[k - 1]; ii[k - 1] = ti;
                }
            }
        }
        float4 ge = geop[j];
        float cost = cost_fn(gx, gy, gw, gh, iou, ge.x, ge.y, ge.z, b0p[j], dcop[j], true, c0);
        if (cost < cv[TK - 1] || (cost == cv[TK - 1] && j < ci[TK - 1])) {
            cv[TK - 1] = cost; ci[TK - 1] = j;
#pragma unroll
            for (int k = TK - 1; k > 0; k--) {
                if (cv[k] < cv[k - 1] || (cv[k] == cv[k - 1] && ci[k] < ci[k - 1])) {
                    float tv = cv[k]; cv[k] = cv[k - 1]; cv[k - 1] = tv;
                    int ti = ci[k]; ci[k] = ci[k - 1]; ci[k - 1] = ti;
                }
            }
        }
    }

    // stage both lists
#pragma unroll
    for (int k = 0; k < TK; k++) {
        s_iv[tid * TK + k] = iv[k]; s_ii[tid * TK + k] = ii[k];
        s_cv[tid * TK + k] = cv[k]; s_ci[tid * TK + k] = ci[k];
    }
    __syncthreads();

    if (warp == 0) {
        // iou merge (max, tie->min idx) over 128 lists, 4 per lane
        int head[4] = {0, 0, 0, 0};
        float ksum = 0.f;
        for (int r = 0; r < TK; r++) {
            float bv = -2.f; int bi = 0x7fffffff; int bk = 0;
#pragma unroll
            for (int k = 0; k < 4; k++) {
                int l = lane + 32 * k;
                float v = s_iv[l * TK + head[k]]; int idx = s_ii[l * TK + head[k]];
                if (v > bv || (v == bv && idx < bi)) { bv = v; bi = idx; bk = k; }
            }
            float mv = bv; int mi = bi; int ml = lane;
            for (int o = 16; o; o >>= 1) {
                float ov = __shfl_xor_sync(0xffffffffu, mv, o);
                int oi = __shfl_xor_sync(0xffffffffu, mi, o);
                int ol = __shfl_xor_sync(0xffffffffu, ml, o);
                if (ov > mv || (ov == mv && oi < mi)) { mv = ov; mi = oi; ml = ol; }
            }
            ksum += fmaxf(mv, 0.f);
            if (lane == ml) {
#pragma unroll
                for (int k = 0; k < 4; k++) if (k == bk) head[k]++;
            }
        }
        if (lane == 0) {
            int dk = (int)ksum;
            s_dk = (dk < 1) ? 1 : dk;
        }
    } else if (warp == 1) {
        // cost merge (min, tie->min idx)
        int head[4] = {0, 0, 0, 0};
        for (int r = 0; r < TK; r++) {
            float bv = 3.5e38f; int bi = 0x7fffffff; int bk = 0;
#pragma unroll
            for (int k = 0; k < 4; k++) {
                int l = lane + 32 * k;
                float v = s_cv[l * TK + head[k]]; int idx = s_ci[l * TK + head[k]];
                if (v < bv || (v == bv && idx < bi)) { bv = v; bi = idx; bk = k; }
            }
            float mv = bv; int mi = bi; int ml = lane;
            for (int o = 16; o; o >>= 1) {
                float ov = __shfl_xor_sync(0xffffffffu, mv, o);
                int oi = __shfl_xor_sync(0xffffffffu, mi, o);
                int ol = __shfl_xor_sync(0xffffffffu, ml, o);
                if (ov < mv || (ov == mv && oi < mi)) { mv = ov; mi = oi; ml = ol; }
            }
            if (lane == 0) s_pos[r] = mi;
            if (lane == ml) {
#pragma unroll
                for (int k = 0; k < 4; k++) if (k == bk) head[k]++;
            }
        }
    }
    __syncthreads();

    if (tid == 0) {
        int dk = s_dk;
        for (int r = 0; r < dk; r++) {
            int a = d_fglist[b * NA + s_pos[r]];
            atomicAdd(&d_cnt[b * NA + a], 1);
            d_lastg[b * NA + a] = g;
        }
    }
}

__global__ void k_resolve(const float* __restrict__ gtb, const int* __restrict__ gtc,
                          const int* __restrict__ ngts) {
    int i = blockIdx.x * blockDim.x + threadIdx.x;
    if (i >= NB * NA) return;
    int c = d_cnt[i];
    if (c == 0) { d_matched[i] = -1; d_prediou[i] = 0.f; return; }
    int b = i / NA, a = i % NA;
    float4 pb = d_box[i];
    int mg;
    if (c == 1) {
        mg = d_lastg[i];
    } else {
        const float c0 = -logf(1e-8f);
        int n = ngts[b];
        int j = d_fgpos[i];
        float4 ge = d_geo[a];
        float b0s = d_b0sC[b * NA + j];
        float best = 3.5e38f; int bi = 0;
        for (int g = 0; g < NG; g++) {
            const float* gb = gtb + ((size_t)b * NG + g) * 4;
            float gx = gb[0], gy = gb[1], gw = gb[2], gh = gb[3];
            int gc = gtc[b * NG + g];
            float iou = iou_fn(gx, gy, gw, gh, pb);
            float dco = d_dcoC[((size_t)b * NC + gc) * NA + j];
            float cv = cost_fn(gx, gy, gw, gh, iou, ge.x, ge.y, ge.z, b0s, dco, g < n, c0);
            if (cv < best) { best = cv; bi = g; }
        }
        mg = bi;
    }
    d_matched[i] = mg;
    const float* gb = gtb + ((size_t)b * NG + mg) * 4;
    d_prediou[i] = iou_fn(gb[0], gb[1], gb[2], gb[3], pb);
}

__global__ void k_loss(const float* __restrict__ gtb, const int* __restrict__ gtc,
                       const float* __restrict__ f8, const float* __restrict__ f16,
                       const float* __restrict__ f32_) {
    __shared__ float s1[256], s2[256], s3[256];
    __shared__ int   s4[256];
    int tid = threadIdx.x;
    int i = blockIdx.x * blockDim.x + tid;
    float liou = 0.f, lobj = 0.f, lcls = 0.f; int nfg = 0;
    if (i < NB * NA) {
        int b = i / NA, a = i % NA;
        int mg = d_matched[i];
        bool fg = mg >= 0;
        float tgt = fg ? 0.9f : 0.f;
        float x = d_obj[i];
        lobj = fmaxf(x, 0.f) - x * tgt + log1pf(expf(-fabsf(x)));
        if (fg) {
            nfg = 1;
            const float* gb = gtb + ((size_t)b * NG + mg) * 4;
            float gx = gb[0], gy = gb[1], gw = gb[2], gh = gb[3];
            float4 pb = d_box[i];
            float tlx = fmaxf(pb.x - pb.z * 0.5f, gx - gw * 0.5f);
            float tly = fmaxf(pb.y - pb.w * 0.5f, gy - gh * 0.5f);
            float brx = fminf(pb.x + pb.z * 0.5f, gx + gw * 0.5f);
            float bry = fminf(pb.y + pb.w * 0.5f, gy + gh * 0.5f);
            bool en = (tlx < brx) && (tly < bry);
            float inter = en ? (brx - tlx) * (bry - tly) : 0.f;
            float uni = pb.z * pb.w + gw * gh - inter;
            float iou = inter / (uni + 1e-16f);
            liou = 1.f - iou * iou;
            int gc = gtc[b * NG + mg];
            const float* f; int hw, HW;
            if (a < A0)      { f = f8;   hw = a;      HW = 6400; }
            else if (a < A1) { f = f16;  hw = a - A0; HW = 1600; }
            else             { f = f32_; hw = a - A1; HW = 400;  }
            float cl = f[((size_t)b * (5 + NC) + 5 + gc) * HW + hw];
            lcls = d_spsC[b * NA + d_fgpos[i]] - cl * d_prediou[i];
        }
    }
    s1[tid] = liou; s2[tid] = lobj; s3[tid] = lcls; s4[tid] = nfg;
    __syncthreads();
    for (int s = 128; s > 0; s >>= 1) {
        if (tid < s) {
            s1[tid] += s1[tid + s]; s2[tid] += s2[tid + s];
            s3[tid] += s3[tid + s]; s4[tid] += s4[tid + s];
        }
        __syncthreads();
    }
    if (tid == 0) {
        atomicAdd(&d_acc[0], (double)s1[0]);
        atomicAdd(&d_acc[1], (double)s2[0]);
        atomicAdd(&d_acc[2], (double)s3[0]);
        atomicAdd(&d_acc[3], (double)s4[0]);
    }
}

__global__ void k_final(float* out) {
    double nfg = d_acc[3];
    if (nfg < 1.0) nfg = 1.0;
    out[0] = (float)((5.0 * d_acc[0] + d_acc[1] + d_acc[2]) / nfg);
}

// ---------------- launch ----------------
extern "C" void kernel_launch(void* const* d_in, const int* in_sizes, int n_in,
                              void* d_out, int out_size) {
    const float* f8   = (const float*)d_in[0];
    const float* f16  = (const float*)d_in[1];
    const float* f32_ = (const float*)d_in[2];
    const float* gtb  = (const float*)d_in[3];
    const int*   gtc  = (const int*)d_in[4];
    const int*   ngts = (const int*)d_in[5];
    float* out = (float*)d_out;

    const int NBA = NB * NA;
    const int T = 256;
    const int GBA = (NBA + T - 1) / T;

    k_decode_fg<<<dim3(NCH, NB), T>>>(f8, f16, f32_, gtb, ngts);
    k_compact<<<dim3(NCH, NB), T>>>();
    k_clsprep<<<dim3(NCH64, NB), T>>>(f8, f16, f32_);
    k_assign<<<dim3(NG, NB), AT>>>(gtb, gtc, ngts);
    k_resolve<<<GBA, T>>>(gtb, gtc, ngts);
    k_loss<<<GBA, T>>>(gtb, gtc, f8, f16, f32_);
    k_final<<<1, 1>>>(out);
}

// round 11
// speedup vs baseline: 1.7126x; 1.3400x over previous
#include <cuda_runtime.h>
#include <cuda_bf16.h>
#include <math.h>

#define NB 32
#define NG 60
#define NC 80
#define NA 8400
#define A0 6400
#define A1 8000
#define TK 10
#define NCH 33   // ceil(NA/256)
#define NCH64 132 // ceil(NA/64)

typedef unsigned long long u64;

// ---------------- device scratch ----------------
__device__ float4 d_box[NB * NA];
__device__ float  d_obj[NB * NA];
__device__ unsigned char d_fg[NB * NA];
__device__ float4 d_geo[NA];
__device__ int    d_ccnt[NB * NCH];
__device__ int    d_fglist[NB * NA];
__device__ int    d_fgpos[NB * NA];
__device__ int    d_fgcnt[NB];
__device__ float4 d_boxC[NB * NA];
__device__ float4 d_geoC[NB * NA];
__device__ float  d_b0sC[NB * NA];
__device__ float  d_spsC[NB * NA];
__device__ float  d_dcoC[(size_t)NB * NC * NA];
__device__ int    d_cnt[NB * NA];
__device__ int    d_lastg[NB * NA];
__device__ int    d_matched[NB * NA];
__device__ float  d_prediou[NB * NA];
__device__ double d_acc[4];

__device__ __forceinline__ float iou_fn(float gx, float gy, float gw, float gh, float4 pb) {
    float tlx = fmaxf(gx - gw * 0.5f, pb.x - pb.z * 0.5f);
    float tly = fmaxf(gy - gh * 0.5f, pb.y - pb.w * 0.5f);
    float brx = fminf(gx + gw * 0.5f, pb.x + pb.z * 0.5f);
    float bry = fminf(gy + gh * 0.5f, pb.y + pb.w * 0.5f);
    bool en = (tlx < brx) && (tly < bry);
    float inter = en ? (brx - tlx) * (bry - tly) : 0.f;
    return inter / (gw * gh + pb.z * pb.w - inter + 1e-16f);
}

__device__ __forceinline__ float cost_fn(float gx, float gy, float gw, float gh,
                                         float iou, float cxa, float cya, float st,
                                         float b0s, float dco, bool valid, float c0) {
    const float R = 2.5f;
    bool in_box = (cxa > gx - 0.5f * gw) && (cxa < gx + 0.5f * gw) &&
                  (cya > gy - 0.5f * gh) && (cya < gy + 0.5f * gh);
    bool in_ctr = (cxa > gx - R * st) && (cxa < gx + R * st) &&
                  (cya > gy - R * st) && (cya < gy + R * st);
    bool in_both = in_box && in_ctr;
    float lt = (iou == 0.f) ? c0 : -logf(iou + 1e-8f);
    float cost = b0s + dco;
    cost += 3.0f * lt;
    cost += 100000.0f * (1.0f - (in_both ? 1.f : 0.f));
    cost += valid ? 0.f : 1000000000.0f;
    return cost;
}

// ---------------- kernels ----------------
__global__ void k_decode_fg(const float* __restrict__ f8,
                            const float* __restrict__ f16,
                            const float* __restrict__ f32_,
                            const float* __restrict__ gtb,
                            const int* __restrict__ ngts) {
    __shared__ float4 sgt[NG];
    int b = blockIdx.y;
    int n = ngts[b];
    if (threadIdx.x < NG) {
        const float* gbp = gtb + ((size_t)b * NG + threadIdx.x) * 4;
        sgt[threadIdx.x] = make_float4(gbp[0], gbp[1], gbp[2], gbp[3]);
    }
    __syncthreads();
    int a = blockIdx.x * blockDim.x + threadIdx.x;
    bool fg = false;
    if (a < NA) {
        int i = b * NA + a;
        d_cnt[i] = 0;
        if (i < 4) d_acc[i] = 0.0;
        const float* f; int hw, HW, W; float st;
        if (a < A0)      { f = f8;   hw = a;      HW = 6400; W = 80; st = 8.f;  }
        else if (a < A1) { f = f16;  hw = a - A0; HW = 1600; W = 40; st = 16.f; }
        else             { f = f32_; hw = a - A1; HW = 400;  W = 20; st = 32.f; }
        int xi = hw % W, yi = hw / W;
        float gx = (float)xi, gy = (float)yi;
        float cxa = (gx + 0.5f) * st, cya = (gy + 0.5f) * st;
        if (b == 0) d_geo[a] = make_float4(cxa, cya, st, 0.f);
        const float* base = f + (size_t)b * (5 + NC) * HW + hw;
        float tx = base[0 * HW], ty = base[(size_t)1 * HW];
        float tw = base[(size_t)2 * HW], th = base[(size_t)3 * HW];
        float to = base[(size_t)4 * HW];
        d_box[i] = make_float4((tx + gx) * st, (ty + gy) * st, expf(tw) * st, expf(th) * st);
        d_obj[i] = to;
        const float R = 2.5f;
        for (int g = 0; g < n; g++) {
            float4 gb = sgt[g];
            bool in_box = (cxa > gb.x - 0.5f * gb.z) && (cxa < gb.x + 0.5f * gb.z) &&
                          (cya > gb.y - 0.5f * gb.w) && (cya < gb.y + 0.5f * gb.w);
            bool in_ctr = (cxa > gb.x - R * st) && (cxa < gb.x + R * st) &&
                          (cya > gb.y - R * st) && (cya < gb.y + R * st);
            fg = fg || in_box || in_ctr;
        }
        d_fg[i] = fg ? 1 : 0;
    }
    int c = __syncthreads_count(fg ? 1 : 0);
    if (threadIdx.x == 0) d_ccnt[b * NCH + blockIdx.x] = c;
}

__global__ void k_compact() {
    __shared__ int swcnt[8];
    __shared__ int swoff[8];
    __shared__ int s_base;
    int b = blockIdx.y, ch = blockIdx.x, tid = threadIdx.x;
    int warp = tid >> 5, lane = tid & 31;
    if (warp == 0) {
        int v = 0;
        for (int c = lane; c < ch; c += 32) v += d_ccnt[b * NCH + c];
        for (int o = 16; o; o >>= 1) v += __shfl_xor_sync(0xffffffffu, v, o);
        if (lane == 0) s_base = v;
    }
    int a = ch * 256 + tid;
    bool flag = (a < NA) && d_fg[b * NA + a];
    unsigned bal = __ballot_sync(0xffffffffu, flag);
    int intra = __popc(bal & ((1u << lane) - 1u));
    if (lane == 0) swcnt[warp] = __popc(bal);
    __syncthreads();
    if (tid == 0) {
        int s = 0;
        for (int w = 0; w < 8; w++) { swoff[w] = s; s += swcnt[w]; }
        if (ch == NCH - 1) d_fgcnt[b] = s_base + s;
    }
    __syncthreads();
    if (flag) {
        int j = s_base + swoff[warp] + intra;
        d_fglist[b * NA + j] = a;
        d_fgpos[b * NA + a] = j;
        d_boxC[b * NA + j] = d_box[b * NA + a];
        d_geoC[b * NA + j] = d_geo[a];
    }
}

__global__ void k_clsprep(const float* __restrict__ f8, const float* __restrict__ f16,
                          const float* __restrict__ f32_) {
    __shared__ float s_b0[256];
    __shared__ float s_sp[256];
    int b = blockIdx.y;
    int tid = threadIdx.x;
    int jl = tid & 63;
    int grp = tid >> 6;
    int j = blockIdx.x * 64 + jl;
    int cnt = d_fgcnt[b];
    float b0s = 0.f, sps = 0.f;
    if (j < cnt) {
        int a = d_fglist[b * NA + j];
        const float* f; int hw, HW;
        if (a < A0)      { f = f8;   hw = a;      HW = 6400; }
        else if (a < A1) { f = f16;  hw = a - A0; HW = 1600; }
        else             { f = f32_; hw = a - A1; HW = 400;  }
        const float* base = f + (size_t)b * (5 + NC) * HW + hw;
        float to = d_obj[b * NA + a];
        float eo = expf(-fabsf(to));
        float so = (to >= 0.f) ? 1.f / (1.f + eo) : eo / (1.f + eo);
        float spo = fmaxf(-to, 0.f) + log1pf(eo);
        int c0i = grp * 20;
#pragma unroll 5
        for (int c = c0i; c < c0i + 20; c++) {
            float x = base[(size_t)(5 + c) * HW];
            float e = expf(-fabsf(x));
            float r = 1.f / (1.f + e);
            float sc = (x >= 0.f) ? r : e * r;
            float l1pe = log1pf(e);
            float sp = fmaxf(x, 0.f) + l1pe;
            float spn = sp - x;
            float p = sqrtf(sc * so);
            p = fminf(fmaxf(p, 1e-7f), 1.f - 1e-7f);
            float bce1 = 0.5f * (spn + spo);
            float bce0 = -logf(1.f - p);
            b0s += bce0;
            d_dcoC[((size_t)b * NC + c) * NA + j] = bce1 - bce0;
            sps += sp;
        }
    }
    s_b0[tid] = b0s;
    s_sp[tid] = sps;
    __syncthreads();
    if (grp == 0 && j < cnt) {
        float tb = (s_b0[jl] + s_b0[64 + jl]) + (s_b0[128 + jl] + s_b0[192 + jl]);
        float ts = (s_sp[jl] + s_sp[64 + jl]) + (s_sp[128 + jl] + s_sp[192 + jl]);
        d_b0sC[b * NA + j] = tb;
        d_spsC[b * NA + j] = ts;
    }
}

// block-per-(b,g), 256 threads; u64 packed keys; hierarchical (warp -> block) merges
__global__ void k_assign(const float* __restrict__ gtb, const int* __restrict__ gtc,
                         const int* __restrict__ ngts) {
    __shared__ u64 s_k[256 * TK];    // 20KB, reused for iou then cost
    __shared__ u64 s_l2[8 * TK];
    __shared__ int s_pos[TK];
    __shared__ int s_dk;

    int tid = threadIdx.x;
    int warp = tid >> 5, lane = tid & 31;
    int g = blockIdx.x, b = blockIdx.y;
    if (g >= ngts[b]) return;

    const float c0 = -logf(1e-8f);

    const float* gb = gtb + ((size_t)b * NG + g) * 4;
    float gx = gb[0], gy = gb[1], gw = gb[2], gh = gb[3];
    int gc = gtc[b * NG + g];
    int cnt = d_fgcnt[b];

    const float4* boxp = d_boxC + b * NA;
    const float4* geop = d_geoC + b * NA;
    const float* b0p = d_b0sC + b * NA;
    const float* dcop = d_dcoC + ((size_t)b * NC + gc) * NA;

    // packed keys: iou max key = (bits(iou)<<32)|~j  (iou>=0, unique); sentinel 0
    //              cost min key = (bits(cost)<<32)|j (cost>0, unique); sentinel MAX
    u64 il[TK], cl[TK];
#pragma unroll
    for (int k = 0; k < TK; k++) { il[k] = 0ull; cl[k] = 0xFFFFFFFFFFFFFFFFull; }

    for (int j = tid; j < cnt; j += 256) {
        float4 pb = boxp[j];
        float iou = iou_fn(gx, gy, gw, gh, pb);
        u64 ik = ((u64)__float_as_uint(iou) << 32) | (unsigned)(~j);
        if (ik > il[TK - 1]) {
            il[TK - 1] = ik;
#pragma unroll
            for (int k = TK - 1; k > 0; k--)
                if (il[k] > il[k - 1]) { u64 t = il[k]; il[k] = il[k - 1]; il[k - 1] = t; }
        }
        float4 ge = geop[j];
        float cost = cost_fn(gx, gy, gw, gh, iou, ge.x, ge.y, ge.z, b0p[j], dcop[j], true, c0);
        u64 ck = ((u64)__float_as_uint(cost) << 32) | (unsigned)j;
        if (ck < cl[TK - 1]) {
            cl[TK - 1] = ck;
#pragma unroll
            for (int k = TK - 1; k > 0; k--)
                if (cl[k] < cl[k - 1]) { u64 t = cl[k]; cl[k] = cl[k - 1]; cl[k - 1] = t; }
        }
    }

    // ================= Phase A: iou -> dyn_k =================
#pragma unroll
    for (int k = 0; k < TK; k++) s_k[tid * TK + k] = il[k];
    __syncthreads();
    {   // level-1: each warp merges its 32 lists (max)
        int head = 0;
        int row = tid;  // each lane owns its own row
        for (int r = 0; r < TK; r++) {
            u64 mk = (head < TK) ? s_k[row * TK + head] : 0ull;
            int ml = lane;
            for (int o = 16; o; o >>= 1) {
                u64 ok = __shfl_xor_sync(0xffffffffu, mk, o);
                int ol = __shfl_xor_sync(0xffffffffu, ml, o);
                if (ok > mk) { mk = ok; ml = ol; }
            }
            if (lane == ml) head++;
            if (lane == 0) s_l2[warp * TK + r] = mk;
        }
    }
    __syncthreads();
    if (warp == 0) {  // level-2: merge 8 warp lists (max)
        int head = 0;
        float ksum = 0.f;
        for (int r = 0; r < TK; r++) {
            u64 mk = (lane < 8 && head < TK) ? s_l2[lane * TK + head] : 0ull;
            int ml = lane;
            for (int o = 16; o; o >>= 1) {
                u64 ok = __shfl_xor_sync(0xffffffffu, mk, o);
                int ol = __shfl_xor_sync(0xffffffffu, ml, o);
                if (ok > mk) { mk = ok; ml = ol; }
            }
            if (lane == ml) head++;
            ksum += __uint_as_float((unsigned)(mk >> 32));
        }
        if (lane == 0) {
            int dk = (int)ksum;
            s_dk = (dk < 1) ? 1 : dk;
        }
    }
    __syncthreads();

    // ================= Phase B: cost -> pos + scatter =================
#pragma unroll
    for (int k = 0; k < TK; k++) s_k[tid * TK + k] = cl[k];
    __syncthreads();
    {   // level-1 (min)
        int head = 0;
        int row = tid;
        for (int r = 0; r < TK; r++) {
            u64 mk = (head < TK) ? s_k[row * TK + head] : 0xFFFFFFFFFFFFFFFFull;
            int ml = lane;
            for (int o = 16; o; o >>= 1) {
                u64 ok = __shfl_xor_sync(0xffffffffu, mk, o);
                int ol = __shfl_xor_sync(0xffffffffu, ml, o);
                if (ok < mk) { mk = ok; ml = ol; }
            }
            if (lane == ml) head++;
            if (lane == 0) s_l2[warp * TK + r] = mk;
        }
    }
    __syncthreads();
    if (warp == 0) {  // level-2 (min)
        int head = 0;
        for (int r = 0; r < TK; r++) {
            u64 mk = (lane < 8 && head < TK) ? s_l2[lane * TK + head] : 0xFFFFFFFFFFFFFFFFull;
            int ml = lane;
            for (int o = 16; o; o >>= 1) {
                u64 ok = __shfl_xor_sync(0xffffffffu, mk, o);
                int ol = __shfl_xor_sync(0xffffffffu, ml, o);
                if (ok < mk) { mk = ok; ml = ol; }
            }
            if (lane == ml) head++;
            if (lane == 0) s_pos[r] = (int)(unsigned)mk;
        }
        if (lane == 0) {
            int dk = s_dk;
            for (int r = 0; r < dk; r++) {
                int a = d_fglist[b * NA + s_pos[r]];
                atomicAdd(&d_cnt[b * NA + a], 1);
                d_lastg[b * NA + a] = g;
            }
        }
    }
}

__global__ void k_resolve(const float* __restrict__ gtb, const int* __restrict__ gtc,
                          const int* __restrict__ ngts) {
    int i = blockIdx.x * blockDim.x + threadIdx.x;
    if (i >= NB * NA) return;
    int c = d_cnt[i];
    if (c == 0) { d_matched[i] = -1; d_prediou[i] = 0.f; return; }
    int b = i / NA, a = i % NA;
    float4 pb = d_box[i];
    int mg;
    if (c == 1) {
        mg = d_lastg[i];
    } else {
        const float c0 = -logf(1e-8f);
        int n = ngts[b];
        int j = d_fgpos[i];
        float4 ge = d_geo[a];
        float b0s = d_b0sC[b * NA + j];
        float best = 3.5e38f; int bi = 0;
        for (int g = 0; g < NG; g++) {
            const float* gb = gtb + ((size_t)b * NG + g) * 4;
            float gx = gb[0], gy = gb[1], gw = gb[2], gh = gb[3];
            int gc = gtc[b * NG + g];
            float iou = iou_fn(gx, gy, gw, gh, pb);
            float dco = d_dcoC[((size_t)b * NC + gc) * NA + j];
            float cv = cost_fn(gx, gy, gw, gh, iou, ge.x, ge.y, ge.z, b0s, dco, g < n, c0);
            if (cv < best) { best = cv; bi = g; }
        }
        mg = bi;
    }
    d_matched[i] = mg;
    const float* gb = gtb + ((size_t)b * NG + mg) * 4;
    d_prediou[i] = iou_fn(gb[0], gb[1], gb[2], gb[3], pb);
}

__global__ void k_loss(const float* __restrict__ gtb, const int* __restrict__ gtc,
                       const float* __restrict__ f8, const float* __restrict__ f16,
                       const float* __restrict__ f32_) {
    __shared__ float s1[256], s2[256], s3[256];
    __shared__ int   s4[256];
    int tid = threadIdx.x;
    int i = blockIdx.x * blockDim.x + tid;
    float liou = 0.f, lobj = 0.f, lcls = 0.f; int nfg = 0;
    if (i < NB * NA) {
        int b = i / NA, a = i % NA;
        int mg = d_matched[i];
        bool fg = mg >= 0;
        float tgt = fg ? 0.9f : 0.f;
        float x = d_obj[i];
        lobj = fmaxf(x, 0.f) - x * tgt + log1pf(expf(-fabsf(x)));
        if (fg) {
            nfg = 1;
            const float* gb = gtb + ((size_t)b * NG + mg) * 4;
            float gx = gb[0], gy = gb[1], gw = gb[2], gh = gb[3];
            float4 pb = d_box[i];
            float tlx = fmaxf(pb.x - pb.z * 0.5f, gx - gw * 0.5f);
            float tly = fmaxf(pb.y - pb.w * 0.5f, gy - gh * 0.5f);
            float brx = fminf(pb.x + pb.z * 0.5f, gx + gw * 0.5f);
            float bry = fminf(pb.y + pb.w * 0.5f, gy + gh * 0.5f);
            bool en = (tlx < brx) && (tly < bry);
            float inter = en ? (brx - tlx) * (bry - tly) : 0.f;
            float uni = pb.z * pb.w + gw * gh - inter;
            float iou = inter / (uni + 1e-16f);
            liou = 1.f - iou * iou;
            int gc = gtc[b * NG + mg];
            const float* f; int hw, HW;
            if (a < A0)      { f = f8;   hw = a;      HW = 6400; }
            else if (a < A1) { f = f16;  hw = a - A0; HW = 1600; }
            else             { f = f32_; hw = a - A1; HW = 400;  }
            float cl = f[((size_t)b * (5 + NC) + 5 + gc) * HW + hw];
            lcls = d_spsC[b * NA + d_fgpos[i]] - cl * d_prediou[i];
        }
    }
    s1[tid] = liou; s2[tid] = lobj; s3[tid] = lcls; s4[tid] = nfg;
    __syncthreads();
    for (int s = 128; s > 0; s >>= 1) {
        if (tid < s) {
            s1[tid] += s1[tid + s]; s2[tid] += s2[tid + s];
            s3[tid] += s3[tid + s]; s4[tid] += s4[tid + s];
        }
        __syncthreads();
    }
    if (tid == 0) {
        atomicAdd(&d_acc[0], (double)s1[0]);
        atomicAdd(&d_acc[1], (double)s2[0]);
        atomicAdd(&d_acc[2], (double)s3[0]);
        atomicAdd(&d_acc[3], (double)s4[0]);
    }
}

__global__ void k_final(float* out) {
    double nfg = d_acc[3];
    if (nfg < 1.0) nfg = 1.0;
    out[0] = (float)((5.0 * d_acc[0] + d_acc[1] + d_acc[2]) / nfg);
}

// ---------------- launch ----------------
extern "C" void kernel_launch(void* const* d_in, const int* in_sizes, int n_in,
                              void* d_out, int out_size) {
    const float* f8   = (const float*)d_in[0];
    const float* f16  = (const float*)d_in[1];
    const float* f32_ = (const float*)d_in[2];
    const float* gtb  = (const float*)d_in[3];
    const int*   gtc  = (const int*)d_in[4];
    const int*   ngts = (const int*)d_in[5];
    float* out = (float*)d_out;

    const int NBA = NB * NA;
    const int T = 256;
    const int GBA = (NBA + T - 1) / T;

    k_decode_fg<<<dim3(NCH, NB), T>>>(f8, f16, f32_, gtb, ngts);
    k_compact<<<dim3(NCH, NB), T>>>();
    k_clsprep<<<dim3(NCH64, NB), T>>>(f8, f16, f32_);
    k_assign<<<dim3(NG, NB), T>>>(gtb, gtc, ngts);
    k_resolve<<<GBA, T>>>(gtb, gtc, ngts);
    k_loss<<<GBA, T>>>(gtb, gtc, f8, f16, f32_);
    k_final<<<1, 1>>>(out);
}

// round 12
// speedup vs baseline: 1.7757x; 1.0369x over previous
#include <cuda_runtime.h>
#include <cuda_bf16.h>
#include <math.h>

#define NB 32
#define NG 60
#define NC 80
#define NA 8400
#define A0 6400
#define A1 8000
#define TK 10
#define NCH 33   // ceil(NA/256)
#define NCH64 132 // ceil(NA/64)

typedef unsigned long long u64;

// ---------------- device scratch ----------------
__device__ float4 d_box[NB * NA];
__device__ float  d_obj[NB * NA];
__device__ unsigned char d_fg[NB * NA];
__device__ float4 d_geo[NA];
__device__ int    d_ccnt[NB * NCH];
__device__ int    d_fglist[NB * NA];
__device__ int    d_fgpos[NB * NA];
__device__ int    d_fgcnt[NB];
__device__ float4 d_boxC[NB * NA];
__device__ float4 d_geoC[NB * NA];
__device__ float  d_b0sC[NB * NA];
__device__ float  d_spsC[NB * NA];
__device__ float  d_dcoC[(size_t)NB * NC * NA];
__device__ int    d_cnt[NB * NA];
__device__ int    d_lastg[NB * NA];
__device__ int    d_matched[NB * NA];
__device__ float  d_prediou[NB * NA];
__device__ double d_acc[4];

__device__ __forceinline__ float iou_fn(float gx, float gy, float gw, float gh, float4 pb) {
    float tlx = fmaxf(gx - gw * 0.5f, pb.x - pb.z * 0.5f);
    float tly = fmaxf(gy - gh * 0.5f, pb.y - pb.w * 0.5f);
    float brx = fminf(gx + gw * 0.5f, pb.x + pb.z * 0.5f);
    float bry = fminf(gy + gh * 0.5f, pb.y + pb.w * 0.5f);
    bool en = (tlx < brx) && (tly < bry);
    float inter = en ? (brx - tlx) * (bry - tly) : 0.f;
    return inter / (gw * gh + pb.z * pb.w - inter + 1e-16f);
}

__device__ __forceinline__ float cost_fn(float gx, float gy, float gw, float gh,
                                         float iou, float cxa, float cya, float st,
                                         float b0s, float dco, bool valid, float c0) {
    const float R = 2.5f;
    bool in_box = (cxa > gx - 0.5f * gw) && (cxa < gx + 0.5f * gw) &&
                  (cya > gy - 0.5f * gh) && (cya < gy + 0.5f * gh);
    bool in_ctr = (cxa > gx - R * st) && (cxa < gx + R * st) &&
                  (cya > gy - R * st) && (cya < gy + R * st);
    bool in_both = in_box && in_ctr;
    float lt = (iou == 0.f) ? c0 : -__logf(iou + 1e-8f);
    float cost = b0s + dco;
    cost += 3.0f * lt;
    cost += 100000.0f * (1.0f - (in_both ? 1.f : 0.f));
    cost += valid ? 0.f : 1000000000.0f;
    return cost;
}

// ---------------- kernels ----------------
__global__ void k_decode_fg(const float* __restrict__ f8,
                            const float* __restrict__ f16,
                            const float* __restrict__ f32_,
                            const float* __restrict__ gtb,
                            const int* __restrict__ ngts) {
    __shared__ float4 sgt[NG];
    int b = blockIdx.y;
    int n = ngts[b];
    if (threadIdx.x < NG) {
        const float* gbp = gtb + ((size_t)b * NG + threadIdx.x) * 4;
        sgt[threadIdx.x] = make_float4(gbp[0], gbp[1], gbp[2], gbp[3]);
    }
    __syncthreads();
    int a = blockIdx.x * blockDim.x + threadIdx.x;
    bool fg = false;
    if (a < NA) {
        int i = b * NA + a;
        d_cnt[i] = 0;
        if (i < 4) d_acc[i] = 0.0;
        const float* f; int hw, HW, W; float st;
        if (a < A0)      { f = f8;   hw = a;      HW = 6400; W = 80; st = 8.f;  }
        else if (a < A1) { f = f16;  hw = a - A0; HW = 1600; W = 40; st = 16.f; }
        else             { f = f32_; hw = a - A1; HW = 400;  W = 20; st = 32.f; }
        int xi = hw % W, yi = hw / W;
        float gx = (float)xi, gy = (float)yi;
        float cxa = (gx + 0.5f) * st, cya = (gy + 0.5f) * st;
        if (b == 0) d_geo[a] = make_float4(cxa, cya, st, 0.f);
        const float* base = f + (size_t)b * (5 + NC) * HW + hw;
        float tx = base[0 * HW], ty = base[(size_t)1 * HW];
        float tw = base[(size_t)2 * HW], th = base[(size_t)3 * HW];
        float to = base[(size_t)4 * HW];
        d_box[i] = make_float4((tx + gx) * st, (ty + gy) * st, __expf(tw) * st, __expf(th) * st);
        d_obj[i] = to;
        const float R = 2.5f;
        for (int g = 0; g < n; g++) {
            float4 gb = sgt[g];
            bool in_box = (cxa > gb.x - 0.5f * gb.z) && (cxa < gb.x + 0.5f * gb.z) &&
                          (cya > gb.y - 0.5f * gb.w) && (cya < gb.y + 0.5f * gb.w);
            bool in_ctr = (cxa > gb.x - R * st) && (cxa < gb.x + R * st) &&
                          (cya > gb.y - R * st) && (cya < gb.y + R * st);
            fg = fg || in_box || in_ctr;
        }
        d_fg[i] = fg ? 1 : 0;
    }
    int c = __syncthreads_count(fg ? 1 : 0);
    if (threadIdx.x == 0) d_ccnt[b * NCH + blockIdx.x] = c;
}

__global__ void k_compact() {
    __shared__ int swcnt[8];
    __shared__ int swoff[8];
    __shared__ int s_base;
    int b = blockIdx.y, ch = blockIdx.x, tid = threadIdx.x;
    int warp = tid >> 5, lane = tid & 31;
    if (warp == 0) {
        int v = 0;
        for (int c = lane; c < ch; c += 32) v += d_ccnt[b * NCH + c];
        for (int o = 16; o; o >>= 1) v += __shfl_xor_sync(0xffffffffu, v, o);
        if (lane == 0) s_base = v;
    }
    int a = ch * 256 + tid;
    bool flag = (a < NA) && d_fg[b * NA + a];
    unsigned bal = __ballot_sync(0xffffffffu, flag);
    int intra = __popc(bal & ((1u << lane) - 1u));
    if (lane == 0) swcnt[warp] = __popc(bal);
    __syncthreads();
    if (tid == 0) {
        int s = 0;
        for (int w = 0; w < 8; w++) { swoff[w] = s; s += swcnt[w]; }
        if (ch == NCH - 1) d_fgcnt[b] = s_base + s;
    }
    __syncthreads();
    if (flag) {
        int j = s_base + swoff[warp] + intra;
        d_fglist[b * NA + j] = a;
        d_fgpos[b * NA + a] = j;
        d_boxC[b * NA + j] = d_box[b * NA + a];
        d_geoC[b * NA + j] = d_geo[a];
    }
}

__global__ void k_clsprep(const float* __restrict__ f8, const float* __restrict__ f16,
                          const float* __restrict__ f32_) {
    __shared__ float s_b0[256];
    __shared__ float s_sp[256];
    int b = blockIdx.y;
    int tid = threadIdx.x;
    int jl = tid & 63;
    int grp = tid >> 6;
    int j = blockIdx.x * 64 + jl;
    int cnt = d_fgcnt[b];
    float b0s = 0.f, sps = 0.f;
    if (j < cnt) {
        int a = d_fglist[b * NA + j];
        const float* f; int hw, HW;
        if (a < A0)      { f = f8;   hw = a;      HW = 6400; }
        else if (a < A1) { f = f16;  hw = a - A0; HW = 1600; }
        else             { f = f32_; hw = a - A1; HW = 400;  }
        const float* base = f + (size_t)b * (5 + NC) * HW + hw;
        float to = d_obj[b * NA + a];
        float eo = __expf(-fabsf(to));
        float so = (to >= 0.f) ? 1.f / (1.f + eo) : eo / (1.f + eo);
        float spo = fmaxf(-to, 0.f) + __logf(1.f + eo);   // softplus(-to)
        int c0i = grp * 20;
#pragma unroll 5
        for (int c = c0i; c < c0i + 20; c++) {
            float x = base[(size_t)(5 + c) * HW];
            float e = __expf(-fabsf(x));
            float r = 1.f / (1.f + e);
            float sc = (x >= 0.f) ? r : e * r;
            float l1pe = __logf(1.f + e);
            float sp = fmaxf(x, 0.f) + l1pe;        // softplus(x)
            float spn = sp - x;                      // softplus(-x)
            float p = sqrtf(sc * so);
            p = fminf(fmaxf(p, 1e-7f), 1.f - 1e-7f);
            float bce1 = 0.5f * (spn + spo);
            float bce0 = -__logf(1.f - p);
            b0s += bce0;
            d_dcoC[((size_t)b * NC + c) * NA + j] = bce1 - bce0;
            sps += sp;
        }
    }
    s_b0[tid] = b0s;
    s_sp[tid] = sps;
    __syncthreads();
    if (grp == 0 && j < cnt) {
        float tb = (s_b0[jl] + s_b0[64 + jl]) + (s_b0[128 + jl] + s_b0[192 + jl]);
        float ts = (s_sp[jl] + s_sp[64 + jl]) + (s_sp[128 + jl] + s_sp[192 + jl]);
        d_b0sC[b * NA + j] = tb;
        d_spsC[b * NA + j] = ts;
    }
}

// block-per-(b,g), 256 threads; u64 packed keys; hierarchical (warp -> block) merges
__global__ void k_assign(const float* __restrict__ gtb, const int* __restrict__ gtc,
                         const int* __restrict__ ngts) {
    __shared__ u64 s_k[256 * TK];    // 20KB, reused for iou then cost
    __shared__ u64 s_l2[8 * TK];
    __shared__ int s_pos[TK];
    __shared__ int s_dk;

    int tid = threadIdx.x;
    int warp = tid >> 5, lane = tid & 31;
    int g = blockIdx.x, b = blockIdx.y;
    if (g >= ngts[b]) return;

    const float c0 = -__logf(1e-8f);

    const float* gb = gtb + ((size_t)b * NG + g) * 4;
    float gx = gb[0], gy = gb[1], gw = gb[2], gh = gb[3];
    int gc = gtc[b * NG + g];
    int cnt = d_fgcnt[b];

    const float4* boxp = d_boxC + b * NA;
    const float4* geop = d_geoC + b * NA;
    const float* b0p = d_b0sC + b * NA;
    const float* dcop = d_dcoC + ((size_t)b * NC + gc) * NA;

    u64 il[TK], cl[TK];
#pragma unroll
    for (int k = 0; k < TK; k++) { il[k] = 0ull; cl[k] = 0xFFFFFFFFFFFFFFFFull; }

    for (int j = tid; j < cnt; j += 256) {
        float4 pb = boxp[j];
        float iou = iou_fn(gx, gy, gw, gh, pb);
        u64 ik = ((u64)__float_as_uint(iou) << 32) | (unsigned)(~j);
        if (ik > il[TK - 1]) {
            il[TK - 1] = ik;
#pragma unroll
            for (int k = TK - 1; k > 0; k--)
                if (il[k] > il[k - 1]) { u64 t = il[k]; il[k] = il[k - 1]; il[k - 1] = t; }
        }
        float4 ge = geop[j];
        float cost = cost_fn(gx, gy, gw, gh, iou, ge.x, ge.y, ge.z, b0p[j], dcop[j], true, c0);
        u64 ck = ((u64)__float_as_uint(cost) << 32) | (unsigned)j;
        if (ck < cl[TK - 1]) {
            cl[TK - 1] = ck;
#pragma unroll
            for (int k = TK - 1; k > 0; k--)
                if (cl[k] < cl[k - 1]) { u64 t = cl[k]; cl[k] = cl[k - 1]; cl[k - 1] = t; }
        }
    }

    // ================= Phase A: iou -> dyn_k =================
#pragma unroll
    for (int k = 0; k < TK; k++) s_k[tid * TK + k] = il[k];
    __syncthreads();
    {
        int head = 0;
        int row = tid;
        for (int r = 0; r < TK; r++) {
            u64 mk = (head < TK) ? s_k[row * TK + head] : 0ull;
            int ml = lane;
            for (int o = 16; o; o >>= 1) {
                u64 ok = __shfl_xor_sync(0xffffffffu, mk, o);
                int ol = __shfl_xor_sync(0xffffffffu, ml, o);
                if (ok > mk) { mk = ok; ml = ol; }
            }
            if (lane == ml) head++;
            if (lane == 0) s_l2[warp * TK + r] = mk;
        }
    }
    __syncthreads();
    if (warp == 0) {
        int head = 0;
        float ksum = 0.f;
        for (int r = 0; r < TK; r++) {
            u64 mk = (lane < 8 && head < TK) ? s_l2[lane * TK + head] : 0ull;
            int ml = lane;
            for (int o = 16; o; o >>= 1) {
                u64 ok = __shfl_xor_sync(0xffffffffu, mk, o);
                int ol = __shfl_xor_sync(0xffffffffu, ml, o);
                if (ok > mk) { mk = ok; ml = ol; }
            }
            if (lane == ml) head++;
            ksum += __uint_as_float((unsigned)(mk >> 32));
        }
        if (lane == 0) {
            int dk = (int)ksum;
            s_dk = (dk < 1) ? 1 : dk;
        }
    }
    __syncthreads();

    // ================= Phase B: cost -> pos + scatter =================
#pragma unroll
    for (int k = 0; k < TK; k++) s_k[tid * TK + k] = cl[k];
    __syncthreads();
    {
        int head = 0;
        int row = tid;
        for (int r = 0; r < TK; r++) {
            u64 mk = (head < TK) ? s_k[row * TK + head] : 0xFFFFFFFFFFFFFFFFull;
            int ml = lane;
            for (int o = 16; o; o >>= 1) {
                u64 ok = __shfl_xor_sync(0xffffffffu, mk, o);
                int ol = __shfl_xor_sync(0xffffffffu, ml, o);
                if (ok < mk) { mk = ok; ml = ol; }
            }
            if (lane == ml) head++;
            if (lane == 0) s_l2[warp * TK + r] = mk;
        }
    }
    __syncthreads();
    if (warp == 0) {
        int head = 0;
        for (int r = 0; r < TK; r++) {
            u64 mk = (lane < 8 && head < TK) ? s_l2[lane * TK + head] : 0xFFFFFFFFFFFFFFFFull;
            int ml = lane;
            for (int o = 16; o; o >>= 1) {
                u64 ok = __shfl_xor_sync(0xffffffffu, mk, o);
                int ol = __shfl_xor_sync(0xffffffffu, ml, o);
                if (ok < mk) { mk = ok; ml = ol; }
            }
            if (lane == ml) head++;
            if (lane == 0) s_pos[r] = (int)(unsigned)mk;
        }
        if (lane == 0) {
            int dk = s_dk;
            for (int r = 0; r < dk; r++) {
                int a = d_fglist[b * NA + s_pos[r]];
                atomicAdd(&d_cnt[b * NA + a], 1);
                d_lastg[b * NA + a] = g;
            }
        }
    }
}

__global__ void k_resolve(const float* __restrict__ gtb, const int* __restrict__ gtc,
                          const int* __restrict__ ngts) {
    int i = blockIdx.x * blockDim.x + threadIdx.x;
    if (i >= NB * NA) return;
    int c = d_cnt[i];
    if (c == 0) { d_matched[i] = -1; d_prediou[i] = 0.f; return; }
    int b = i / NA, a = i % NA;
    float4 pb = d_box[i];
    int mg;
    if (c == 1) {
        mg = d_lastg[i];
    } else {
        const float c0 = -__logf(1e-8f);
        int n = ngts[b];
        int j = d_fgpos[i];
        float4 ge = d_geo[a];
        float b0s = d_b0sC[b * NA + j];
        float best = 3.5e38f; int bi = 0;
        for (int g = 0; g < NG; g++) {
            const float* gb = gtb + ((size_t)b * NG + g) * 4;
            float gx = gb[0], gy = gb[1], gw = gb[2], gh = gb[3];
            int gc = gtc[b * NG + g];
            float iou = iou_fn(gx, gy, gw, gh, pb);
            float dco = d_dcoC[((size_t)b * NC + gc) * NA + j];
            float cv = cost_fn(gx, gy, gw, gh, iou, ge.x, ge.y, ge.z, b0s, dco, g < n, c0);
            if (cv < best) { best = cv; bi = g; }
        }
        mg = bi;
    }
    d_matched[i] = mg;
    const float* gb = gtb + ((size_t)b * NG + mg) * 4;
    d_prediou[i] = iou_fn(gb[0], gb[1], gb[2], gb[3], pb);
}

__global__ void k_loss(const float* __restrict__ gtb, const int* __restrict__ gtc,
                       const float* __restrict__ f8, const float* __restrict__ f16,
                       const float* __restrict__ f32_) {
    __shared__ float s1[256], s2[256], s3[256];
    __shared__ int   s4[256];
    int tid = threadIdx.x;
    int i = blockIdx.x * blockDim.x + tid;
    float liou = 0.f, lobj = 0.f, lcls = 0.f; int nfg = 0;
    if (i < NB * NA) {
        int b = i / NA, a = i % NA;
        int mg = d_matched[i];
        bool fg = mg >= 0;
        float tgt = fg ? 0.9f : 0.f;
        float x = d_obj[i];
        lobj = fmaxf(x, 0.f) - x * tgt + __logf(1.f + __expf(-fabsf(x)));
        if (fg) {
            nfg = 1;
            const float* gb = gtb + ((size_t)b * NG + mg) * 4;
            float gx = gb[0], gy = gb[1], gw = gb[2], gh = gb[3];
            float4 pb = d_box[i];
            float tlx = fmaxf(pb.x - pb.z * 0.5f, gx - gw * 0.5f);
            float tly = fmaxf(pb.y - pb.w * 0.5f, gy - gh * 0.5f);
            float brx = fminf(pb.x + pb.z * 0.5f, gx + gw * 0.5f);
            float bry = fminf(pb.y + pb.w * 0.5f, gy + gh * 0.5f);
            bool en = (tlx < brx) && (tly < bry);
            float inter = en ? (brx - tlx) * (bry - tly) : 0.f;
            float uni = pb.z * pb.w + gw * gh - inter;
            float iou = inter / (uni + 1e-16f);
            liou = 1.f - iou * iou;
            int gc = gtc[b * NG + mg];
            const float* f; int hw, HW;
            if (a < A0)      { f = f8;   hw = a;      HW = 6400; }
            else if (a < A1) { f = f16;  hw = a - A0; HW = 1600; }
            else             { f = f32_; hw = a - A1; HW = 400;  }
            float cl = f[((size_t)b * (5 + NC) + 5 + gc) * HW + hw];
            lcls = d_spsC[b * NA + d_fgpos[i]] - cl * d_prediou[i];
        }
    }
    s1[tid] = liou; s2[tid] = lobj; s3[tid] = lcls; s4[tid] = nfg;
    __syncthreads();
    for (int s = 128; s > 0; s >>= 1) {
        if (tid < s) {
            s1[tid] += s1[tid + s]; s2[tid] += s2[tid + s];
            s3[tid] += s3[tid + s]; s4[tid] += s4[tid + s];
        }
        __syncthreads();
    }
    if (tid == 0) {
        atomicAdd(&d_acc[0], (double)s1[0]);
        atomicAdd(&d_acc[1], (double)s2[0]);
        atomicAdd(&d_acc[2], (double)s3[0]);
        atomicAdd(&d_acc[3], (double)s4[0]);
    }
}

__global__ void k_final(float* out) {
    double nfg = d_acc[3];
    if (nfg < 1.0) nfg = 1.0;
    out[0] = (float)((5.0 * d_acc[0] + d_acc[1] + d_acc[2]) / nfg);
}

// ---------------- launch ----------------
extern "C" void kernel_launch(void* const* d_in, const int* in_sizes, int n_in,
                              void* d_out, int out_size) {
    const float* f8   = (const float*)d_in[0];
    const float* f16  = (const float*)d_in[1];
    const float* f32_ = (const float*)d_in[2];
    const float* gtb  = (const float*)d_in[3];
    const int*   gtc  = (const int*)d_in[4];
    const int*   ngts = (const int*)d_in[5];
    float* out = (float*)d_out;

    const int NBA = NB * NA;
    const int T = 256;
    const int GBA = (NBA + T - 1) / T;

    k_decode_fg<<<dim3(NCH, NB), T>>>(f8, f16, f32_, gtb, ngts);
    k_compact<<<dim3(NCH, NB), T>>>();
    k_clsprep<<<dim3(NCH64, NB), T>>>(f8, f16, f32_);
    k_assign<<<dim3(NG, NB), T>>>(gtb, gtc, ngts);
    k_resolve<<<GBA, T>>>(gtb, gtc, ngts);
    k_loss<<<GBA, T>>>(gtb, gtc, f8, f16, f32_);
    k_final<<<1, 1>>>(out);
}

// round 13
// speedup vs baseline: 1.8255x; 1.0280x over previous
#include <cuda_runtime.h>
#include <cuda_bf16.h>
#include <math.h>

#define NB 32
#define NG 60
#define NC 80
#define NA 8400
#define A0 6400
#define A1 8000
#define TK 10
#define NCH 33   // ceil(NA/256)
#define NCH64 132 // ceil(NA/64)

typedef unsigned long long u64;

// ---------------- device scratch ----------------
__device__ float4 d_box[NB * NA];
__device__ float  d_obj[NB * NA];
__device__ unsigned char d_fg[NB * NA];
__device__ float4 d_geo[NA];
__device__ int    d_ccnt[NB * NCH];
__device__ int    d_fglist[NB * NA];
__device__ int    d_fgpos[NB * NA];
__device__ int    d_fgcnt[NB];
__device__ float4 d_boxC[NB * NA];
__device__ float4 d_geoC[NB * NA];
__device__ float  d_b0sC[NB * NA];
__device__ float  d_spsC[NB * NA];
__device__ float  d_dcoC[(size_t)NB * NC * NA];
__device__ int    d_cnt[NB * NA];
__device__ int    d_lastg[NB * NA];
__device__ int    d_matched[NB * NA];
__device__ float  d_prediou[NB * NA];
__device__ double d_acc[4];

__device__ __forceinline__ float iou_fn(float gx, float gy, float gw, float gh, float4 pb) {
    float tlx = fmaxf(gx - gw * 0.5f, pb.x - pb.z * 0.5f);
    float tly = fmaxf(gy - gh * 0.5f, pb.y - pb.w * 0.5f);
    float brx = fminf(gx + gw * 0.5f, pb.x + pb.z * 0.5f);
    float bry = fminf(gy + gh * 0.5f, pb.y + pb.w * 0.5f);
    bool en = (tlx < brx) && (tly < bry);
    float inter = en ? (brx - tlx) * (bry - tly) : 0.f;
    return inter / (gw * gh + pb.z * pb.w - inter + 1e-16f);
}

__device__ __forceinline__ float cost_fn(float gx, float gy, float gw, float gh,
                                         float iou, float cxa, float cya, float st,
                                         float b0s, float dco, bool valid, float c0) {
    const float R = 2.5f;
    bool in_box = (cxa > gx - 0.5f * gw) && (cxa < gx + 0.5f * gw) &&
                  (cya > gy - 0.5f * gh) && (cya < gy + 0.5f * gh);
    bool in_ctr = (cxa > gx - R * st) && (cxa < gx + R * st) &&
                  (cya > gy - R * st) && (cya < gy + R * st);
    bool in_both = in_box && in_ctr;
    float lt = (iou == 0.f) ? c0 : -__logf(iou + 1e-8f);
    float cost = b0s + dco;
    cost += 3.0f * lt;
    cost += 100000.0f * (1.0f - (in_both ? 1.f : 0.f));
    cost += valid ? 0.f : 1000000000.0f;
    return cost;
}

// ---------------- kernels ----------------
__global__ void k_decode_fg(const float* __restrict__ f8,
                            const float* __restrict__ f16,
                            const float* __restrict__ f32_,
                            const float* __restrict__ gtb,
                            const int* __restrict__ ngts) {
    __shared__ float4 sgt[NG];
    int b = blockIdx.y;
    int n = ngts[b];
    if (threadIdx.x < NG) {
        const float* gbp = gtb + ((size_t)b * NG + threadIdx.x) * 4;
        sgt[threadIdx.x] = make_float4(gbp[0], gbp[1], gbp[2], gbp[3]);
    }
    __syncthreads();
    int a = blockIdx.x * blockDim.x + threadIdx.x;
    bool fg = false;
    if (a < NA) {
        int i = b * NA + a;
        d_cnt[i] = 0;
        if (i < 4) d_acc[i] = 0.0;
        const float* f; int hw, HW, W; float st;
        if (a < A0)      { f = f8;   hw = a;      HW = 6400; W = 80; st = 8.f;  }
        else if (a < A1) { f = f16;  hw = a - A0; HW = 1600; W = 40; st = 16.f; }
        else             { f = f32_; hw = a - A1; HW = 400;  W = 20; st = 32.f; }
        int xi = hw % W, yi = hw / W;
        float gx = (float)xi, gy = (float)yi;
        float cxa = (gx + 0.5f) * st, cya = (gy + 0.5f) * st;
        if (b == 0) d_geo[a] = make_float4(cxa, cya, st, 0.f);
        const float* base = f + (size_t)b * (5 + NC) * HW + hw;
        float tx = base[0 * HW], ty = base[(size_t)1 * HW];
        float tw = base[(size_t)2 * HW], th = base[(size_t)3 * HW];
        float to = base[(size_t)4 * HW];
        d_box[i] = make_float4((tx + gx) * st, (ty + gy) * st, __expf(tw) * st, __expf(th) * st);
        d_obj[i] = to;
        const float R = 2.5f;
        for (int g = 0; g < n; g++) {
            float4 gb = sgt[g];
            bool in_box = (cxa > gb.x - 0.5f * gb.z) && (cxa < gb.x + 0.5f * gb.z) &&
                          (cya > gb.y - 0.5f * gb.w) && (cya < gb.y + 0.5f * gb.w);
            bool in_ctr = (cxa > gb.x - R * st) && (cxa < gb.x + R * st) &&
                          (cya > gb.y - R * st) && (cya < gb.y + R * st);
            fg = fg || in_box || in_ctr;
        }
        d_fg[i] = fg ? 1 : 0;
    }
    int c = __syncthreads_count(fg ? 1 : 0);
    if (threadIdx.x == 0) d_ccnt[b * NCH + blockIdx.x] = c;
}

__global__ void k_compact() {
    __shared__ int swcnt[8];
    __shared__ int swoff[8];
    __shared__ int s_base;
    int b = blockIdx.y, ch = blockIdx.x, tid = threadIdx.x;
    int warp = tid >> 5, lane = tid & 31;
    if (warp == 0) {
        int v = 0;
        for (int c = lane; c < ch; c += 32) v += d_ccnt[b * NCH + c];
        for (int o = 16; o; o >>= 1) v += __shfl_xor_sync(0xffffffffu, v, o);
        if (lane == 0) s_base = v;
    }
    int a = ch * 256 + tid;
    bool flag = (a < NA) && d_fg[b * NA + a];
    unsigned bal = __ballot_sync(0xffffffffu, flag);
    int intra = __popc(bal & ((1u << lane) - 1u));
    if (lane == 0) swcnt[warp] = __popc(bal);
    __syncthreads();
    if (tid == 0) {
        int s = 0;
        for (int w = 0; w < 8; w++) { swoff[w] = s; s += swcnt[w]; }
        if (ch == NCH - 1) d_fgcnt[b] = s_base + s;
    }
    __syncthreads();
    if (flag) {
        int j = s_base + swoff[warp] + intra;
        d_fglist[b * NA + j] = a;
        d_fgpos[b * NA + a] = j;
        d_boxC[b * NA + j] = d_box[b * NA + a];
        d_geoC[b * NA + j] = d_geo[a];
    }
}

__global__ void k_clsprep(const float* __restrict__ f8, const float* __restrict__ f16,
                          const float* __restrict__ f32_) {
    __shared__ float s_b0[256];
    __shared__ float s_sp[256];
    int b = blockIdx.y;
    int tid = threadIdx.x;
    int jl = tid & 63;
    int grp = tid >> 6;
    int j = blockIdx.x * 64 + jl;
    int cnt = d_fgcnt[b];
    float b0s = 0.f, sps = 0.f;
    if (j < cnt) {
        int a = d_fglist[b * NA + j];
        const float* f; int hw, HW;
        if (a < A0)      { f = f8;   hw = a;      HW = 6400; }
        else if (a < A1) { f = f16;  hw = a - A0; HW = 1600; }
        else             { f = f32_; hw = a - A1; HW = 400;  }
        const float* base = f + (size_t)b * (5 + NC) * HW + hw;
        float to = d_obj[b * NA + a];
        float eo = __expf(-fabsf(to));
        float so = (to >= 0.f) ? 1.f / (1.f + eo) : eo / (1.f + eo);
        float spo = fmaxf(-to, 0.f) + __logf(1.f + eo);   // softplus(-to)
        int c0i = grp * 20;
#pragma unroll 5
        for (int c = c0i; c < c0i + 20; c++) {
            float x = base[(size_t)(5 + c) * HW];
            float e = __expf(-fabsf(x));
            float r = 1.f / (1.f + e);
            float sc = (x >= 0.f) ? r : e * r;
            float l1pe = __logf(1.f + e);
            float sp = fmaxf(x, 0.f) + l1pe;
            float spn = sp - x;
            float p = sqrtf(sc * so);
            p = fminf(fmaxf(p, 1e-7f), 1.f - 1e-7f);
            float bce1 = 0.5f * (spn + spo);
            float bce0 = -__logf(1.f - p);
            b0s += bce0;
            d_dcoC[((size_t)b * NC + c) * NA + j] = bce1 - bce0;
            sps += sp;
        }
    }
    s_b0[tid] = b0s;
    s_sp[tid] = sps;
    __syncthreads();
    if (grp == 0 && j < cnt) {
        float tb = (s_b0[jl] + s_b0[64 + jl]) + (s_b0[128 + jl] + s_b0[192 + jl]);
        float ts = (s_sp[jl] + s_sp[64 + jl]) + (s_sp[128 + jl] + s_sp[192 + jl]);
        d_b0sC[b * NA + j] = tb;
        d_spsC[b * NA + j] = ts;
    }
}

// block-per-(b,g), 256 threads; unsorted smem rows, argmax-extraction merges
__global__ void k_assign(const float* __restrict__ gtb, const int* __restrict__ gtc,
                         const int* __restrict__ ngts) {
    __shared__ u64 s_ik[256 * TK];   // iou keys (unsorted per-thread rows)
    __shared__ u64 s_ck[256 * TK];   // cost keys
    __shared__ u64 s_l2a[8 * TK];    // warp winners, iou
    __shared__ u64 s_l2b[8 * TK];    // warp winners, cost

    int tid = threadIdx.x;
    int warp = tid >> 5, lane = tid & 31;
    int g = blockIdx.x, b = blockIdx.y;
    if (g >= ngts[b]) return;

    const float c0 = -__logf(1e-8f);

    const float* gb = gtb + ((size_t)b * NG + g) * 4;
    float gx = gb[0], gy = gb[1], gw = gb[2], gh = gb[3];
    int gc = gtc[b * NG + g];
    int cnt = d_fgcnt[b];

    const float4* boxp = d_boxC + b * NA;
    const float4* geop = d_geoC + b * NA;
    const float* b0p = d_b0sC + b * NA;
    const float* dcop = d_dcoC + ((size_t)b * NC + gc) * NA;

    u64* irow = &s_ik[tid * TK];
    u64* crow = &s_ck[tid * TK];
#pragma unroll
    for (int k = 0; k < TK; k++) { irow[k] = 0ull; crow[k] = ~0ull; }

    int nloc = 0;
    u64 iworst = 0ull; int iws = 0;     // worst (smallest) iou key when full
    u64 cworst = ~0ull; int cws = 0;    // worst (largest) cost key when full

    for (int j = tid; j < cnt; j += 256) {
        float4 pb = boxp[j];
        float iou = iou_fn(gx, gy, gw, gh, pb);
        u64 ik = ((u64)__float_as_uint(iou) << 32) | (unsigned)(~j);
        float4 ge = geop[j];
        float cost = cost_fn(gx, gy, gw, gh, iou, ge.x, ge.y, ge.z, b0p[j], dcop[j], true, c0);
        u64 ck = ((u64)__float_as_uint(cost) << 32) | (unsigned)j;
        if (nloc < TK) {
            irow[nloc] = ik;
            crow[nloc] = ck;
            nloc++;
            if (nloc == TK) {
                iworst = irow[0]; iws = 0; cworst = crow[0]; cws = 0;
#pragma unroll
                for (int k = 1; k < TK; k++) {
                    u64 v = irow[k]; if (v < iworst) { iworst = v; iws = k; }
                    u64 w2 = crow[k]; if (w2 > cworst) { cworst = w2; cws = k; }
                }
            }
        } else {
            if (ik > iworst) {
                irow[iws] = ik;
                iworst = irow[0]; iws = 0;
#pragma unroll
                for (int k = 1; k < TK; k++) { u64 v = irow[k]; if (v < iworst) { iworst = v; iws = k; } }
            }
            if (ck < cworst) {
                crow[cws] = ck;
                cworst = crow[0]; cws = 0;
#pragma unroll
                for (int k = 1; k < TK; k++) { u64 v = crow[k]; if (v > cworst) { cworst = v; cws = k; } }
            }
        }
    }
    __syncthreads();

    // ---- level-1 A: iou max extraction (all 8 warps, lane owns its row) ----
    {
        u64 bk = irow[0]; int bs = 0;
#pragma unroll
        for (int k = 1; k < TK; k++) { u64 v = irow[k]; if (v > bk) { bk = v; bs = k; } }
        for (int r = 0; r < TK; r++) {
            u64 mk = bk; int ml = lane;
            for (int o = 16; o; o >>= 1) {
                u64 ok = __shfl_xor_sync(0xffffffffu, mk, o);
                int ol = __shfl_xor_sync(0xffffffffu, ml, o);
                if (ok > mk) { mk = ok; ml = ol; }
            }
            if (lane == 0) s_l2a[warp * TK + r] = mk;
            if (ml == lane) {
                irow[bs] = 0ull;
                bk = irow[0]; bs = 0;
#pragma unroll
                for (int k = 1; k < TK; k++) { u64 v = irow[k]; if (v > bk) { bk = v; bs = k; } }
            }
        }
    }
    // ---- level-1 B: cost min extraction ----
    {
        u64 bk = crow[0]; int bs = 0;
#pragma unroll
        for (int k = 1; k < TK; k++) { u64 v = crow[k]; if (v < bk) { bk = v; bs = k; } }
        for (int r = 0; r < TK; r++) {
            u64 mk = bk; int ml = lane;
            for (int o = 16; o; o >>= 1) {
                u64 ok = __shfl_xor_sync(0xffffffffu, mk, o);
                int ol = __shfl_xor_sync(0xffffffffu, ml, o);
                if (ok < mk) { mk = ok; ml = ol; }
            }
            if (lane == 0) s_l2b[warp * TK + r] = mk;
            if (ml == lane) {
                crow[bs] = ~0ull;
                bk = crow[0]; bs = 0;
#pragma unroll
                for (int k = 1; k < TK; k++) { u64 v = crow[k]; if (v < bk) { bk = v; bs = k; } }
            }
        }
    }
    __syncthreads();

    if (warp == 0) {
        // level-2 A: max over 8 sorted warp lists -> dyn_k
        int head = 0;
        float ksum = 0.f;
        for (int r = 0; r < TK; r++) {
            u64 mk = (lane < 8 && head < TK) ? s_l2a[lane * TK + head] : 0ull;
            int ml = lane;
            for (int o = 16; o; o >>= 1) {
                u64 ok = __shfl_xor_sync(0xffffffffu, mk, o);
                int ol = __shfl_xor_sync(0xffffffffu, ml, o);
                if (ok > mk) { mk = ok; ml = ol; }
            }
            if (lane == ml) head++;
            ksum += __uint_as_float((unsigned)(mk >> 32));
        }
        int dk = (int)ksum;
        if (dk < 1) dk = 1;

        // level-2 B: min -> pos + scatter
        head = 0;
        int pa[TK];
        for (int r = 0; r < TK; r++) {
            u64 mk = (lane < 8 && head < TK) ? s_l2b[lane * TK + head] : ~0ull;
            int ml = lane;
            for (int o = 16; o; o >>= 1) {
                u64 ok = __shfl_xor_sync(0xffffffffu, mk, o);
                int ol = __shfl_xor_sync(0xffffffffu, ml, o);
                if (ok < mk) { mk = ok; ml = ol; }
            }
            if (lane == ml) head++;
            pa[r] = (int)(unsigned)mk;
        }
        if (lane == 0) {
            for (int r = 0; r < dk; r++) {
                int a = d_fglist[b * NA + pa[r]];
                atomicAdd(&d_cnt[b * NA + a], 1);
                d_lastg[b * NA + a] = g;
            }
        }
    }
}

__global__ void k_resolve(const float* __restrict__ gtb, const int* __restrict__ gtc,
                          const int* __restrict__ ngts) {
    int i = blockIdx.x * blockDim.x + threadIdx.x;
    if (i >= NB * NA) return;
    int c = d_cnt[i];
    if (c == 0) { d_matched[i] = -1; d_prediou[i] = 0.f; return; }
    int b = i / NA, a = i % NA;
    float4 pb = d_box[i];
    int mg;
    if (c == 1) {
        mg = d_lastg[i];
    } else {
        const float c0 = -__logf(1e-8f);
        int n = ngts[b];
        int j = d_fgpos[i];
        float4 ge = d_geo[a];
        float b0s = d_b0sC[b * NA + j];
        float best = 3.5e38f; int bi = 0;
        for (int g = 0; g < NG; g++) {
            const float* gb = gtb + ((size_t)b * NG + g) * 4;
            float gx = gb[0], gy = gb[1], gw = gb[2], gh = gb[3];
            int gc = gtc[b * NG + g];
            float iou = iou_fn(gx, gy, gw, gh, pb);
            float dco = d_dcoC[((size_t)b * NC + gc) * NA + j];
            float cv = cost_fn(gx, gy, gw, gh, iou, ge.x, ge.y, ge.z, b0s, dco, g < n, c0);
            if (cv < best) { best = cv; bi = g; }
        }
        mg = bi;
    }
    d_matched[i] = mg;
    const float* gb = gtb + ((size_t)b * NG + mg) * 4;
    d_prediou[i] = iou_fn(gb[0], gb[1], gb[2], gb[3], pb);
}

__global__ void k_loss(const float* __restrict__ gtb, const int* __restrict__ gtc,
                       const float* __restrict__ f8, const float* __restrict__ f16,
                       const float* __restrict__ f32_) {
    __shared__ float s1[256], s2[256], s3[256];
    __shared__ int   s4[256];
    int tid = threadIdx.x;
    int i = blockIdx.x * blockDim.x + tid;
    float liou = 0.f, lobj = 0.f, lcls = 0.f; int nfg = 0;
    if (i < NB * NA) {
        int b = i / NA, a = i % NA;
        int mg = d_matched[i];
        bool fg = mg >= 0;
        float tgt = fg ? 0.9f : 0.f;
        float x = d_obj[i];
        lobj = fmaxf(x, 0.f) - x * tgt + __logf(1.f + __expf(-fabsf(x)));
        if (fg) {
            nfg = 1;
            const float* gb = gtb + ((size_t)b * NG + mg) * 4;
            float gx = gb[0], gy = gb[1], gw = gb[2], gh = gb[3];
            float4 pb = d_box[i];
            float tlx = fmaxf(pb.x - pb.z * 0.5f, gx - gw * 0.5f);
            float tly = fmaxf(pb.y - pb.w * 0.5f, gy - gh * 0.5f);
            float brx = fminf(pb.x + pb.z * 0.5f, gx + gw * 0.5f);
            float bry = fminf(pb.y + pb.w * 0.5f, gy + gh * 0.5f);
            bool en = (tlx < brx) && (tly < bry);
            float inter = en ? (brx - tlx) * (bry - tly) : 0.f;
            float uni = pb.z * pb.w + gw * gh - inter;
            float iou = inter / (uni + 1e-16f);
            liou = 1.f - iou * iou;
            int gc = gtc[b * NG + mg];
            const float* f; int hw, HW;
            if (a < A0)      { f = f8;   hw = a;      HW = 6400; }
            else if (a < A1) { f = f16;  hw = a - A0; HW = 1600; }
            else             { f = f32_; hw = a - A1; HW = 400;  }
            float cl = f[((size_t)b * (5 + NC) + 5 + gc) * HW + hw];
            lcls = d_spsC[b * NA + d_fgpos[i]] - cl * d_prediou[i];
        }
    }
    s1[tid] = liou; s2[tid] = lobj; s3[tid] = lcls; s4[tid] = nfg;
    __syncthreads();
    for (int s = 128; s > 0; s >>= 1) {
        if (tid < s) {
            s1[tid] += s1[tid + s]; s2[tid] += s2[tid + s];
            s3[tid] += s3[tid + s]; s4[tid] += s4[tid + s];
        }
        __syncthreads();
    }
    if (tid == 0) {
        atomicAdd(&d_acc[0], (double)s1[0]);
        atomicAdd(&d_acc[1], (double)s2[0]);
        atomicAdd(&d_acc[2], (double)s3[0]);
        atomicAdd(&d_acc[3], (double)s4[0]);
    }
}

__global__ void k_final(float* out) {
    double nfg = d_acc[3];
    if (nfg < 1.0) nfg = 1.0;
    out[0] = (float)((5.0 * d_acc[0] + d_acc[1] + d_acc[2]) / nfg);
}

// ---------------- launch ----------------
extern "C" void kernel_launch(void* const* d_in, const int* in_sizes, int n_in,
                              void* d_out, int out_size) {
    const float* f8   = (const float*)d_in[0];
    const float* f16  = (const float*)d_in[1];
    const float* f32_ = (const float*)d_in[2];
    const float* gtb  = (const float*)d_in[3];
    const int*   gtc  = (const int*)d_in[4];
    const int*   ngts = (const int*)d_in[5];
    float* out = (float*)d_out;

    const int NBA = NB * NA;
    const int T = 256;
    const int GBA = (NBA + T - 1) / T;

    k_decode_fg<<<dim3(NCH, NB), T>>>(f8, f16, f32_, gtb, ngts);
    k_compact<<<dim3(NCH, NB), T>>>();
    k_clsprep<<<dim3(NCH64, NB), T>>>(f8, f16, f32_);
    k_assign<<<dim3(NG, NB), T>>>(gtb, gtc, ngts);
    k_resolve<<<GBA, T>>>(gtb, gtc, ngts);
    k_loss<<<GBA, T>>>(gtb, gtc, f8, f16, f32_);
    k_final<<<1, 1>>>(out);
}

// round 14
// speedup vs baseline: 1.9441x; 1.0650x over previous
#include <cuda_runtime.h>
#include <cuda_bf16.h>
#include <math.h>

#define NB 32
#define NG 60
#define NC 80
#define NA 8400
#define A0 6400
#define A1 8000
#define TK 10
#define NCH 33   // ceil(NA/256)
#define NCH64 132 // ceil(NA/64)

typedef unsigned long long u64;

// ---------------- device scratch ----------------
__device__ float4 d_box[NB * NA];
__device__ float  d_obj[NB * NA];
__device__ unsigned char d_fg[NB * NA];
__device__ float4 d_geo[NA];
__device__ int    d_ccnt[NB * NCH];
__device__ int    d_fglist[NB * NA];
__device__ int    d_fgpos[NB * NA];
__device__ int    d_fgcnt[NB];
__device__ float4 d_boxC[NB * NA];
__device__ float4 d_geoC[NB * NA];
__device__ float  d_b0sC[NB * NA];
__device__ float  d_spsC[NB * NA];
__device__ float  d_dcoC[(size_t)NB * NC * NA];
__device__ int    d_cnt[NB * NA];
__device__ int    d_lastg[NB * NA];
__device__ double d_acc[4];

__device__ __forceinline__ float iou_fn(float gx, float gy, float gw, float gh, float4 pb) {
    float tlx = fmaxf(gx - gw * 0.5f, pb.x - pb.z * 0.5f);
    float tly = fmaxf(gy - gh * 0.5f, pb.y - pb.w * 0.5f);
    float brx = fminf(gx + gw * 0.5f, pb.x + pb.z * 0.5f);
    float bry = fminf(gy + gh * 0.5f, pb.y + pb.w * 0.5f);
    bool en = (tlx < brx) && (tly < bry);
    float inter = en ? (brx - tlx) * (bry - tly) : 0.f;
    return inter / (gw * gh + pb.z * pb.w - inter + 1e-16f);
}

__device__ __forceinline__ float cost_fn(float gx, float gy, float gw, float gh,
                                         float iou, float cxa, float cya, float st,
                                         float b0s, float dco, bool valid, float c0) {
    const float R = 2.5f;
    bool in_box = (cxa > gx - 0.5f * gw) && (cxa < gx + 0.5f * gw) &&
                  (cya > gy - 0.5f * gh) && (cya < gy + 0.5f * gh);
    bool in_ctr = (cxa > gx - R * st) && (cxa < gx + R * st) &&
                  (cya > gy - R * st) && (cya < gy + R * st);
    bool in_both = in_box && in_ctr;
    float lt = (iou == 0.f) ? c0 : -__logf(iou + 1e-8f);
    float cost = b0s + dco;
    cost += 3.0f * lt;
    cost += 100000.0f * (1.0f - (in_both ? 1.f : 0.f));
    cost += valid ? 0.f : 1000000000.0f;
    return cost;
}

// ---------------- kernels ----------------
__global__ void k_decode_fg(const float* __restrict__ f8,
                            const float* __restrict__ f16,
                            const float* __restrict__ f32_,
                            const float* __restrict__ gtb,
                            const int* __restrict__ ngts) {
    __shared__ float4 sgt[NG];
    int b = blockIdx.y;
    int n = ngts[b];
    if (threadIdx.x < NG) {
        const float* gbp = gtb + ((size_t)b * NG + threadIdx.x) * 4;
        sgt[threadIdx.x] = make_float4(gbp[0], gbp[1], gbp[2], gbp[3]);
    }
    __syncthreads();
    int a = blockIdx.x * blockDim.x + threadIdx.x;
    bool fg = false;
    if (a < NA) {
        int i = b * NA + a;
        d_cnt[i] = 0;
        if (i < 4) d_acc[i] = 0.0;
        const float* f; int hw, HW, W; float st;
        if (a < A0)      { f = f8;   hw = a;      HW = 6400; W = 80; st = 8.f;  }
        else if (a < A1) { f = f16;  hw = a - A0; HW = 1600; W = 40; st = 16.f; }
        else             { f = f32_; hw = a - A1; HW = 400;  W = 20; st = 32.f; }
        int xi = hw % W, yi = hw / W;
        float gx = (float)xi, gy = (float)yi;
        float cxa = (gx + 0.5f) * st, cya = (gy + 0.5f) * st;
        if (b == 0) d_geo[a] = make_float4(cxa, cya, st, 0.f);
        const float* base = f + (size_t)b * (5 + NC) * HW + hw;
        float tx = base[0 * HW], ty = base[(size_t)1 * HW];
        float tw = base[(size_t)2 * HW], th = base[(size_t)3 * HW];
        float to = base[(size_t)4 * HW];
        d_box[i] = make_float4((tx + gx) * st, (ty + gy) * st, __expf(tw) * st, __expf(th) * st);
        d_obj[i] = to;
        const float R = 2.5f;
        for (int g = 0; g < n; g++) {
            float4 gb = sgt[g];
            bool in_box = (cxa > gb.x - 0.5f * gb.z) && (cxa < gb.x + 0.5f * gb.z) &&
                          (cya > gb.y - 0.5f * gb.w) && (cya < gb.y + 0.5f * gb.w);
            bool in_ctr = (cxa > gb.x - R * st) && (cxa < gb.x + R * st) &&
                          (cya > gb.y - R * st) && (cya < gb.y + R * st);
            fg = fg || in_box || in_ctr;
        }
        d_fg[i] = fg ? 1 : 0;
    }
    int c = __syncthreads_count(fg ? 1 : 0);
    if (threadIdx.x == 0) d_ccnt[b * NCH + blockIdx.x] = c;
}

__global__ void k_compact() {
    __shared__ int swcnt[8];
    __shared__ int swoff[8];
    __shared__ int s_base;
    int b = blockIdx.y, ch = blockIdx.x, tid = threadIdx.x;
    int warp = tid >> 5, lane = tid & 31;
    if (warp == 0) {
        int v = 0;
        for (int c = lane; c < ch; c += 32) v += d_ccnt[b * NCH + c];
        for (int o = 16; o; o >>= 1) v += __shfl_xor_sync(0xffffffffu, v, o);
        if (lane == 0) s_base = v;
    }
    int a = ch * 256 + tid;
    bool flag = (a < NA) && d_fg[b * NA + a];
    unsigned bal = __ballot_sync(0xffffffffu, flag);
    int intra = __popc(bal & ((1u << lane) - 1u));
    if (lane == 0) swcnt[warp] = __popc(bal);
    __syncthreads();
    if (tid == 0) {
        int s = 0;
        for (int w = 0; w < 8; w++) { swoff[w] = s; s += swcnt[w]; }
        if (ch == NCH - 1) d_fgcnt[b] = s_base + s;
    }
    __syncthreads();
    if (flag) {
        int j = s_base + swoff[warp] + intra;
        d_fglist[b * NA + j] = a;
        d_fgpos[b * NA + a] = j;
        d_boxC[b * NA + j] = d_box[b * NA + a];
        d_geoC[b * NA + j] = d_geo[a];
    }
}

__global__ void k_clsprep(const float* __restrict__ f8, const float* __restrict__ f16,
                          const float* __restrict__ f32_) {
    __shared__ float s_b0[256];
    __shared__ float s_sp[256];
    int b = blockIdx.y;
    int tid = threadIdx.x;
    int jl = tid & 63;
    int grp = tid >> 6;
    int j = blockIdx.x * 64 + jl;
    int cnt = d_fgcnt[b];
    float b0s = 0.f, sps = 0.f;
    if (j < cnt) {
        int a = d_fglist[b * NA + j];
        const float* f; int hw, HW;
        if (a < A0)      { f = f8;   hw = a;      HW = 6400; }
        else if (a < A1) { f = f16;  hw = a - A0; HW = 1600; }
        else             { f = f32_; hw = a - A1; HW = 400;  }
        const float* base = f + (size_t)b * (5 + NC) * HW + hw;
        float to = d_obj[b * NA + a];
        float eo = __expf(-fabsf(to));
        float so = (to >= 0.f) ? 1.f / (1.f + eo) : eo / (1.f + eo);
        float spo = fmaxf(-to, 0.f) + __logf(1.f + eo);   // softplus(-to)
        int c0i = grp * 20;
#pragma unroll 5
        for (int c = c0i; c < c0i + 20; c++) {
            float x = base[(size_t)(5 + c) * HW];
            float e = __expf(-fabsf(x));
            float r = 1.f / (1.f + e);
            float sc = (x >= 0.f) ? r : e * r;
            float l1pe = __logf(1.f + e);
            float sp = fmaxf(x, 0.f) + l1pe;
            float spn = sp - x;
            float p = sqrtf(sc * so);
            p = fminf(fmaxf(p, 1e-7f), 1.f - 1e-7f);
            float bce1 = 0.5f * (spn + spo);
            float bce0 = -__logf(1.f - p);
            b0s += bce0;
            d_dcoC[((size_t)b * NC + c) * NA + j] = bce1 - bce0;
            sps += sp;
        }
    }
    s_b0[tid] = b0s;
    s_sp[tid] = sps;
    __syncthreads();
    if (grp == 0 && j < cnt) {
        float tb = (s_b0[jl] + s_b0[64 + jl]) + (s_b0[128 + jl] + s_b0[192 + jl]);
        float ts = (s_sp[jl] + s_sp[64 + jl]) + (s_sp[128 + jl] + s_sp[192 + jl]);
        d_b0sC[b * NA + j] = tb;
        d_spsC[b * NA + j] = ts;
    }
}

// block-per-(b,g), 256 threads; unsorted smem rows; iou-list skips iou==0
__global__ void k_assign(const float* __restrict__ gtb, const int* __restrict__ gtc,
                         const int* __restrict__ ngts) {
    __shared__ u64 s_ik[256 * TK];
    __shared__ u64 s_ck[256 * TK];
    __shared__ u64 s_l2a[8 * TK];
    __shared__ u64 s_l2b[8 * TK];

    int tid = threadIdx.x;
    int warp = tid >> 5, lane = tid & 31;
    int g = blockIdx.x, b = blockIdx.y;
    if (g >= ngts[b]) return;

    const float c0 = -__logf(1e-8f);

    const float* gb = gtb + ((size_t)b * NG + g) * 4;
    float gx = gb[0], gy = gb[1], gw = gb[2], gh = gb[3];
    int gc = gtc[b * NG + g];
    int cnt = d_fgcnt[b];

    const float4* boxp = d_boxC + b * NA;
    const float4* geop = d_geoC + b * NA;
    const float* b0p = d_b0sC + b * NA;
    const float* dcop = d_dcoC + ((size_t)b * NC + gc) * NA;

    u64* irow = &s_ik[tid * TK];
    u64* crow = &s_ck[tid * TK];
#pragma unroll
    for (int k = 0; k < TK; k++) { irow[k] = 0ull; crow[k] = ~0ull; }

    int iloc = 0, cloc = 0;
    u64 iworst = 0ull; int iws = 0;     // smallest iou key when full
    u64 cworst = ~0ull; int cws = 0;    // largest cost key when full

    for (int j = tid; j < cnt; j += 256) {
        float4 pb = boxp[j];
        float iou = iou_fn(gx, gy, gw, gh, pb);
        // ---- iou list: only iou>0 matters (zeros contribute 0 to ksum) ----
        if (iou > 0.f) {
            u64 ik = ((u64)__float_as_uint(iou) << 32) | (unsigned)(~j);
            if (iloc < TK) {
                irow[iloc++] = ik;
                if (iloc == TK) {
                    iworst = irow[0]; iws = 0;
#pragma unroll
                    for (int k = 1; k < TK; k++) { u64 v = irow[k]; if (v < iworst) { iworst = v; iws = k; } }
                }
            } else if (ik > iworst) {
                irow[iws] = ik;
                iworst = irow[0]; iws = 0;
#pragma unroll
                for (int k = 1; k < TK; k++) { u64 v = irow[k]; if (v < iworst) { iworst = v; iws = k; } }
            }
        }
        // ---- cost list: all elements ----
        float4 ge = geop[j];
        float cost = cost_fn(gx, gy, gw, gh, iou, ge.x, ge.y, ge.z, b0p[j], dcop[j], true, c0);
        u64 ck = ((u64)__float_as_uint(cost) << 32) | (unsigned)j;
        if (cloc < TK) {
            crow[cloc++] = ck;
            if (cloc == TK) {
                cworst = crow[0]; cws = 0;
#pragma unroll
                for (int k = 1; k < TK; k++) { u64 v = crow[k]; if (v > cworst) { cworst = v; cws = k; } }
            }
        } else if (ck < cworst) {
            crow[cws] = ck;
            cworst = crow[0]; cws = 0;
#pragma unroll
            for (int k = 1; k < TK; k++) { u64 v = crow[k]; if (v > cworst) { cworst = v; cws = k; } }
        }
    }
    __syncthreads();

    // ---- level-1 A: iou max extraction ----
    {
        u64 bk = irow[0]; int bs = 0;
#pragma unroll
        for (int k = 1; k < TK; k++) { u64 v = irow[k]; if (v > bk) { bk = v; bs = k; } }
        for (int r = 0; r < TK; r++) {
            u64 mk = bk; int ml = lane;
            for (int o = 16; o; o >>= 1) {
                u64 ok = __shfl_xor_sync(0xffffffffu, mk, o);
                int ol = __shfl_xor_sync(0xffffffffu, ml, o);
                if (ok > mk) { mk = ok; ml = ol; }
            }
            if (lane == 0) s_l2a[warp * TK + r] = mk;
            if (ml == lane) {
                irow[bs] = 0ull;
                bk = irow[0]; bs = 0;
#pragma unroll
                for (int k = 1; k < TK; k++) { u64 v = irow[k]; if (v > bk) { bk = v; bs = k; } }
            }
        }
    }
    // ---- level-1 B: cost min extraction ----
    {
        u64 bk = crow[0]; int bs = 0;
#pragma unroll
        for (int k = 1; k < TK; k++) { u64 v = crow[k]; if (v < bk) { bk = v; bs = k; } }
        for (int r = 0; r < TK; r++) {
            u64 mk = bk; int ml = lane;
            for (int o = 16; o; o >>= 1) {
                u64 ok = __shfl_xor_sync(0xffffffffu, mk, o);
                int ol = __shfl_xor_sync(0xffffffffu, ml, o);
                if (ok < mk) { mk = ok; ml = ol; }
            }
            if (lane == 0) s_l2b[warp * TK + r] = mk;
            if (ml == lane) {
                crow[bs] = ~0ull;
                bk = crow[0]; bs = 0;
#pragma unroll
                for (int k = 1; k < TK; k++) { u64 v = crow[k]; if (v < bk) { bk = v; bs = k; } }
            }
        }
    }
    __syncthreads();

    if (warp == 0) {
        int head = 0;
        float ksum = 0.f;
        for (int r = 0; r < TK; r++) {
            u64 mk = (lane < 8 && head < TK) ? s_l2a[lane * TK + head] : 0ull;
            int ml = lane;
            for (int o = 16; o; o >>= 1) {
                u64 ok = __shfl_xor_sync(0xffffffffu, mk, o);
                int ol = __shfl_xor_sync(0xffffffffu, ml, o);
                if (ok > mk) { mk = ok; ml = ol; }
            }
            if (lane == ml) head++;
            ksum += __uint_as_float((unsigned)(mk >> 32));
        }
        int dk = (int)ksum;
        if (dk < 1) dk = 1;

        head = 0;
        int pa[TK];
        for (int r = 0; r < TK; r++) {
            u64 mk = (lane < 8 && head < TK) ? s_l2b[lane * TK + head] : ~0ull;
            int ml = lane;
            for (int o = 16; o; o >>= 1) {
                u64 ok = __shfl_xor_sync(0xffffffffu, mk, o);
                int ol = __shfl_xor_sync(0xffffffffu, ml, o);
                if (ok < mk) { mk = ok; ml = ol; }
            }
            if (lane == ml) head++;
            pa[r] = (int)(unsigned)mk;
        }
        if (lane == 0) {
            for (int r = 0; r < dk; r++) {
                int a = d_fglist[b * NA + pa[r]];
                atomicAdd(&d_cnt[b * NA + a], 1);
                d_lastg[b * NA + a] = g;
            }
        }
    }
}

// fused resolve + loss: one pass over all (b,a)
__global__ void k_resolve_loss(const float* __restrict__ gtb, const int* __restrict__ gtc,
                               const int* __restrict__ ngts,
                               const float* __restrict__ f8, const float* __restrict__ f16,
                               const float* __restrict__ f32_) {
    __shared__ float s1[256], s2[256], s3[256];
    __shared__ int   s4[256];
    int tid = threadIdx.x;
    int i = blockIdx.x * blockDim.x + tid;
    float liou = 0.f, lobj = 0.f, lcls = 0.f; int nfg = 0;
    if (i < NB * NA) {
        int b = i / NA, a = i % NA;
        int c = d_cnt[i];
        bool fg = c > 0;
        float tgt = fg ? 0.9f : 0.f;
        float x = d_obj[i];
        lobj = fmaxf(x, 0.f) - x * tgt + __logf(1.f + __expf(-fabsf(x)));
        if (fg) {
            nfg = 1;
            float4 pb = d_box[i];
            int j = d_fgpos[i];
            int mg;
            if (c == 1) {
                mg = d_lastg[i];
            } else {
                const float c0 = -__logf(1e-8f);
                int n = ngts[b];
                float4 ge = d_geo[a];
                float b0s = d_b0sC[b * NA + j];
                float best = 3.5e38f; int bi = 0;
                for (int g = 0; g < NG; g++) {
                    const float* gbp = gtb + ((size_t)b * NG + g) * 4;
                    float ggx = gbp[0], ggy = gbp[1], ggw = gbp[2], ggh = gbp[3];
                    int ggc = gtc[b * NG + g];
                    float iou2 = iou_fn(ggx, ggy, ggw, ggh, pb);
                    float dco = d_dcoC[((size_t)b * NC + ggc) * NA + j];
                    float cv = cost_fn(ggx, ggy, ggw, ggh, iou2, ge.x, ge.y, ge.z, b0s, dco, g < n, c0);
                    if (cv < best) { best = cv; bi = g; }
                }
                mg = bi;
            }
            const float* gbp = gtb + ((size_t)b * NG + mg) * 4;
            float gx = gbp[0], gy = gbp[1], gw = gbp[2], gh = gbp[3];
            float prediou = iou_fn(gx, gy, gw, gh, pb);
            // iou loss (same expression as before)
            float tlx = fmaxf(pb.x - pb.z * 0.5f, gx - gw * 0.5f);
            float tly = fmaxf(pb.y - pb.w * 0.5f, gy - gh * 0.5f);
            float brx = fminf(pb.x + pb.z * 0.5f, gx + gw * 0.5f);
            float bry = fminf(pb.y + pb.w * 0.5f, gy + gh * 0.5f);
            bool en = (tlx < brx) && (tly < bry);
            float inter = en ? (brx - tlx) * (bry - tly) : 0.f;
            float uni = pb.z * pb.w + gw * gh - inter;
            float iou = inter / (uni + 1e-16f);
            liou = 1.f - iou * iou;
            int gc = gtc[b * NG + mg];
            const float* f; int hw, HW;
            if (a < A0)      { f = f8;   hw = a;      HW = 6400; }
            else if (a < A1) { f = f16;  hw = a - A0; HW = 1600; }
            else             { f = f32_; hw = a - A1; HW = 400;  }
            float cl = f[((size_t)b * (5 + NC) + 5 + gc) * HW + hw];
            lcls = d_spsC[b * NA + j] - cl * prediou;
        }
    }
    s1[tid] = liou; s2[tid] = lobj; s3[tid] = lcls; s4[tid] = nfg;
    __syncthreads();
    for (int s = 128; s > 0; s >>= 1) {
        if (tid < s) {
            s1[tid] += s1[tid + s]; s2[tid] += s2[tid + s];
            s3[tid] += s3[tid + s]; s4[tid] += s4[tid + s];
        }
        __syncthreads();
    }
    if (tid == 0) {
        atomicAdd(&d_acc[0], (double)s1[0]);
        atomicAdd(&d_acc[1], (double)s2[0]);
        atomicAdd(&d_acc[2], (double)s3[0]);
        atomicAdd(&d_acc[3], (double)s4[0]);
    }
}

__global__ void k_final(float* out) {
    double nfg = d_acc[3];
    if (nfg < 1.0) nfg = 1.0;
    out[0] = (float)((5.0 * d_acc[0] + d_acc[1] + d_acc[2]) / nfg);
}

// ---------------- launch ----------------
extern "C" void kernel_launch(void* const* d_in, const int* in_sizes, int n_in,
                              void* d_out, int out_size) {
    const float* f8   = (const float*)d_in[0];
    const float* f16  = (const float*)d_in[1];
    const float* f32_ = (const float*)d_in[2];
    const float* gtb  = (const float*)d_in[3];
    const int*   gtc  = (const int*)d_in[4];
    const int*   ngts = (const int*)d_in[5];
    float* out = (float*)d_out;

    const int NBA = NB * NA;
    const int T = 256;
    const int GBA = (NBA + T - 1) / T;

    k_decode_fg<<<dim3(NCH, NB), T>>>(f8, f16, f32_, gtb, ngts);
    k_compact<<<dim3(NCH, NB), T>>>();
    k_clsprep<<<dim3(NCH64, NB), T>>>(f8, f16, f32_);
    k_assign<<<dim3(NG, NB), T>>>(gtb, gtc, ngts);
    k_resolve_loss<<<GBA, T>>>(gtb, gtc, ngts, f8, f16, f32_);
    k_final<<<1, 1>>>(out);
}